// round 12
// baseline (speedup 1.0000x reference)
#include <cuda_runtime.h>
#include <cuda_fp16.h>
#include <cstdint>

// Problem constants (fixed by setup_inputs)
#define BB 4
#define TT 1024
#define SS 1024
#define DD 1024
#define HH 16
#define HD 64
#define FFD 4096
#define NROWS (BB*TT)   // 4096
#define LDA3 3072       // fused QKV row stride (halves)

// GEMM tiling (mma.sync fp16, m16n8k16): 128x128 CTA tile, 64x32 warp tile
#define BM 128
#define BN 128
#define BKH 64                        // K halves per stage chunk
#define ROWH 72                       // smem row stride in halves (64 + 8 pad)
#define STAGE_H (2 * BM * ROWH)       // halves per stage (A + B tiles)
#define GEMM_SMEM (3 * STAGE_H * 2)   // 110592 bytes

// Attention (fp16 mma) smem: Q(128) + K(64) + V(64) tiles, register softmax
#define AH 72                         // half row stride
#define ATTN_SMEM ((128 + 64 + 64) * AH * 2)   // 36864 bytes

// ---------------- scratch (device globals; no allocation) ----------------
__device__ float  g_X  [NROWS*DD];
__device__ __half g_LN [NROWS*DD];
__device__ __half g_QKV[NROWS*LDA3];     // fused Q|K|V (self and cross), fp16
__device__ __half g_CTX[NROWS*DD];
__device__ __half g_FF [NROWS*FFD];
__device__ __half g_WT [16*1024*1024];   // transposed fp16 weights
__device__ __half g_ENC[BB*SS*DD];       // fp16 encoder activations
__device__ float  g_B3 [3072];           // concat self q|k|v bias
__device__ float  g_B2 [2048];           // concat cross k|v bias

// ---------------- helpers ----------------
__device__ __forceinline__ uint32_t s2u(const void* p) {
    uint32_t a;
    asm("{ .reg .u64 t; cvta.to.shared.u64 t, %1; cvt.u32.u64 %0, t; }" : "=r"(a) : "l"(p));
    return a;
}
__device__ __forceinline__ void cp16(uint32_t dst, const void* src) {
    asm volatile("cp.async.cg.shared.global [%0], [%1], 16;" :: "r"(dst), "l"(src));
}
__device__ __forceinline__ void cp_commit() { asm volatile("cp.async.commit_group;" ::: "memory"); }
template<int N> __device__ __forceinline__ void cp_wait() {
    asm volatile("cp.async.wait_group %0;" :: "n"(N) : "memory");
}
__device__ __forceinline__ void mma16(float* c, const uint32_t* a, const uint32_t* b) {
    asm volatile(
        "mma.sync.aligned.m16n8k16.row.col.f32.f16.f16.f32 "
        "{%0,%1,%2,%3}, {%4,%5,%6,%7}, {%8,%9}, {%0,%1,%2,%3};"
        : "+f"(c[0]), "+f"(c[1]), "+f"(c[2]), "+f"(c[3])
        : "r"(a[0]), "r"(a[1]), "r"(a[2]), "r"(a[3]), "r"(b[0]), "r"(b[1]));
}
#define LDM4(r0, r1, r2, r3, addr) \
    asm volatile("ldmatrix.sync.aligned.m8n8.x4.shared.b16 {%0,%1,%2,%3}, [%4];" \
        : "=r"(r0), "=r"(r1), "=r"(r2), "=r"(r3) : "r"(addr))
#define LDM4T(r0, r1, r2, r3, addr) \
    asm volatile("ldmatrix.sync.aligned.m8n8.x4.trans.shared.b16 {%0,%1,%2,%3}, [%4];" \
        : "=r"(r0), "=r"(r1), "=r"(r2), "=r"(r3) : "r"(addr))

// ---------------- batched transpose + fp16 round + enc copy ----------------
struct TransArgs {
    const float* s[10];
    __half* d[10];
    const float* enc;
    __half* encd;
};
__global__ void transpose_all(TransArgs ta)
{
    __shared__ float tile[32][33];
    int bid = blockIdx.x;
    int tx = threadIdx.x, ty = threadIdx.y;
    if (bid >= 16384) {
        int i = (bid - 16384) * 256 + ty * 32 + tx;
        float4 v = reinterpret_cast<const float4*>(ta.enc)[i];
        reinterpret_cast<__half2*>(ta.encd)[2*i]   = __floats2half2_rn(v.x, v.y);
        reinterpret_cast<__half2*>(ta.encd)[2*i+1] = __floats2half2_rn(v.z, v.w);
        return;
    }
    const float* src; __half* dst; int R, C, bx, by;
    if (bid < 8192) {
        int w = bid >> 10, tt = bid & 1023;
        src = ta.s[w]; dst = ta.d[w]; R = 1024; C = 1024;
        bx = (tt & 31) * 32; by = (tt >> 5) * 32;
    } else if (bid < 12288) {
        int tt = bid - 8192;
        src = ta.s[8]; dst = ta.d[8]; R = 1024; C = 4096;
        bx = (tt & 127) * 32; by = (tt >> 7) * 32;
    } else {
        int tt = bid - 12288;
        src = ta.s[9]; dst = ta.d[9]; R = 4096; C = 1024;
        bx = (tt & 31) * 32; by = (tt >> 5) * 32;
    }
    #pragma unroll
    for (int j = 0; j < 32; j += 8)
        tile[ty + j][tx] = src[(size_t)(by + ty + j) * C + bx + tx];
    __syncthreads();
    #pragma unroll
    for (int j = 0; j < 32; j += 8)
        dst[(size_t)(bx + ty + j) * R + by + tx] = __float2half_rn(tile[tx][ty + j]);
}

// ---------------- LayerNorm (fp32 in, fp16 out; feeds GEMMs only) -------
__global__ void ln_kernel(const float* __restrict__ x,
                          const float* __restrict__ g,
                          const float* __restrict__ b,
                          __half* __restrict__ y)
{
    int row = blockIdx.x;
    int t = threadIdx.x;
    const float4* xr = reinterpret_cast<const float4*>(x + (size_t)row * DD);
    float4 v = xr[t];
    float s  = v.x + v.y + v.z + v.w;
    float ss = v.x*v.x + v.y*v.y + v.z*v.z + v.w*v.w;
    #pragma unroll
    for (int o = 16; o > 0; o >>= 1) {
        s  += __shfl_xor_sync(0xffffffffu, s,  o);
        ss += __shfl_xor_sync(0xffffffffu, ss, o);
    }
    __shared__ float ws[8], wss[8];
    __shared__ float s_mu, s_rstd;
    int lane = t & 31, wid = t >> 5;
    if (lane == 0) { ws[wid] = s; wss[wid] = ss; }
    __syncthreads();
    if (t == 0) {
        float S = 0.f, SS2 = 0.f;
        #pragma unroll
        for (int i = 0; i < 8; i++) { S += ws[i]; SS2 += wss[i]; }
        float mu = S * (1.0f / DD);
        float var = SS2 * (1.0f / DD) - mu * mu;
        s_mu = mu;
        s_rstd = rsqrtf(var + 1e-5f);
    }
    __syncthreads();
    float mu = s_mu, rstd = s_rstd;
    float4 gg = reinterpret_cast<const float4*>(g)[t];
    float4 bb = reinterpret_cast<const float4*>(b)[t];
    __half2* yr = reinterpret_cast<__half2*>(y + (size_t)row * DD);
    yr[2*t]   = __floats2half2_rn((v.x - mu) * rstd * gg.x + bb.x,
                                  (v.y - mu) * rstd * gg.y + bb.y);
    yr[2*t+1] = __floats2half2_rn((v.z - mu) * rstd * gg.z + bb.z,
                                  (v.w - mu) * rstd * gg.w + bb.w);
}

// ---------------- fp16 mma.sync GEMM (ldmatrix + interleaved prefetch) --
// C[Nrows, Mout] = A[Nrows, K] @ WT[Mout, K]^T + bias (+relu / +res)
// EPI: 1 = bias+relu -> half, 2 = bias+residual -> float, 4 = bias -> half
template<int EPI>
__global__ __launch_bounds__(256, 2)
void gemm_h(const __half* __restrict__ A, const __half* __restrict__ WT,
            const float* __restrict__ bias, const float* __restrict__ res,
            void* __restrict__ Cv, int K, int Mout, int ldc)
{
    extern __shared__ __half smh[];
    const int t = threadIdx.x;
    const int wid = t >> 5, lane = t & 31;
    const int g = lane >> 2, tig = lane & 3;
    const int wm = (wid & 1) * 64;
    const int wn = (wid >> 1) * 32;
    const int n0 = blockIdx.y * BM;
    const int m0 = blockIdx.x * BN;

    const __half* Ab = A  + (size_t)n0 * K;
    const __half* Bb = WT + (size_t)m0 * K;

    const int ldrow = t >> 1;
    const int ldseg = (t & 1) * 32;

    const int laneq = lane >> 3;
    const int lrow8 = lane & 7;
    const int aoff0 = (wm + lrow8 + (laneq & 1) * 8) * ROWH + (laneq >> 1) * 8;
    const int boff0 = BM * ROWH + (wn + lrow8 + (laneq >> 1) * 8) * ROWH + (laneq & 1) * 8;

    float c[4][4][4];
    #pragma unroll
    for (int i = 0; i < 4; i++)
        #pragma unroll
        for (int j = 0; j < 4; j++)
            #pragma unroll
            for (int r = 0; r < 4; r++) c[i][j][r] = 0.f;

    const int NIter = K / BKH;
    uint32_t smbase = s2u(smh);

    #pragma unroll
    for (int p = 0; p < 2; p++) {
        uint32_t sA = smbase + p * STAGE_H * 2;
        uint32_t sB = sA + BM * ROWH * 2;
        const __half* Ak = Ab + p * BKH;
        const __half* Bk = Bb + p * BKH;
        #pragma unroll
        for (int q = 0; q < 2; q++) {
            int seg = ldseg + q * 16;
            cp16(sA + (ldrow * ROWH + seg) * 2,      Ak + (size_t)ldrow * K + seg);
            cp16(sA + (ldrow * ROWH + seg + 8) * 2,  Ak + (size_t)ldrow * K + seg + 8);
            cp16(sB + (ldrow * ROWH + seg) * 2,      Bk + (size_t)ldrow * K + seg);
            cp16(sB + (ldrow * ROWH + seg + 8) * 2,  Bk + (size_t)ldrow * K + seg + 8);
        }
        cp_commit();
    }

    for (int i = 0; i < NIter; i++) {
        cp_wait<1>();
        __syncthreads();

        uint32_t stg = smbase + (uint32_t)((i % 3) * STAGE_H * 2);

        // ks = 0 compute
        {
            uint32_t a[4][4], b[4][2];
            uint32_t aaddr = stg + (uint32_t)(aoff0 * 2);
            #pragma unroll
            for (int fi = 0; fi < 4; fi++)
                LDM4(a[fi][0], a[fi][1], a[fi][2], a[fi][3],
                     aaddr + (uint32_t)(fi * 16 * ROWH * 2));
            uint32_t baddr = stg + (uint32_t)(boff0 * 2);
            #pragma unroll
            for (int p = 0; p < 2; p++) {
                uint32_t r0, r1, r2, r3;
                LDM4(r0, r1, r2, r3, baddr + (uint32_t)(p * 16 * ROWH * 2));
                b[2*p][0] = r0;   b[2*p][1] = r1;
                b[2*p+1][0] = r2; b[2*p+1][1] = r3;
            }
            #pragma unroll
            for (int fi = 0; fi < 4; fi++)
                #pragma unroll
                for (int fj = 0; fj < 4; fj++)
                    mma16(c[fi][fj], a[fi], b[fj]);
        }

        // issue prefetch for i+2
        int ip = i + 2;
        if (ip < NIter) {
            int s = ip % 3;
            uint32_t sA = smbase + s * STAGE_H * 2;
            uint32_t sB = sA + BM * ROWH * 2;
            const __half* Ak = Ab + ip * BKH;
            const __half* Bk = Bb + ip * BKH;
            #pragma unroll
            for (int q = 0; q < 2; q++) {
                int seg = ldseg + q * 16;
                cp16(sA + (ldrow * ROWH + seg) * 2,      Ak + (size_t)ldrow * K + seg);
                cp16(sA + (ldrow * ROWH + seg + 8) * 2,  Ak + (size_t)ldrow * K + seg + 8);
                cp16(sB + (ldrow * ROWH + seg) * 2,      Bk + (size_t)ldrow * K + seg);
                cp16(sB + (ldrow * ROWH + seg + 8) * 2,  Bk + (size_t)ldrow * K + seg + 8);
            }
        }
        cp_commit();

        // ks = 1..3 compute
        #pragma unroll
        for (int ks = 1; ks < 4; ks++) {
            uint32_t a[4][4], b[4][2];
            uint32_t aaddr = stg + (uint32_t)((aoff0 + ks * 16) * 2);
            #pragma unroll
            for (int fi = 0; fi < 4; fi++)
                LDM4(a[fi][0], a[fi][1], a[fi][2], a[fi][3],
                     aaddr + (uint32_t)(fi * 16 * ROWH * 2));
            uint32_t baddr = stg + (uint32_t)((boff0 + ks * 16) * 2);
            #pragma unroll
            for (int p = 0; p < 2; p++) {
                uint32_t r0, r1, r2, r3;
                LDM4(r0, r1, r2, r3, baddr + (uint32_t)(p * 16 * ROWH * 2));
                b[2*p][0] = r0;   b[2*p][1] = r1;
                b[2*p+1][0] = r2; b[2*p+1][1] = r3;
            }
            #pragma unroll
            for (int fi = 0; fi < 4; fi++)
                #pragma unroll
                for (int fj = 0; fj < 4; fj++)
                    mma16(c[fi][fj], a[fi], b[fj]);
        }
    }

    #pragma unroll
    for (int fi = 0; fi < 4; fi++) {
        #pragma unroll
        for (int fj = 0; fj < 4; fj++) {
            int row = n0 + wm + 16 * fi + g;
            int col = m0 + wn + 8 * fj + 2 * tig;
            float b0 = __ldg(bias + col), b1 = __ldg(bias + col + 1);
            float v00 = c[fi][fj][0] + b0, v01 = c[fi][fj][1] + b1;
            float v10 = c[fi][fj][2] + b0, v11 = c[fi][fj][3] + b1;
            size_t o0 = (size_t)row * ldc + col;
            size_t o1 = (size_t)(row + 8) * ldc + col;
            if (EPI == 1) {
                __half* Ch = reinterpret_cast<__half*>(Cv);
                *reinterpret_cast<__half2*>(Ch + o0) =
                    __floats2half2_rn(fmaxf(v00, 0.f), fmaxf(v01, 0.f));
                *reinterpret_cast<__half2*>(Ch + o1) =
                    __floats2half2_rn(fmaxf(v10, 0.f), fmaxf(v11, 0.f));
            } else if (EPI == 2) {
                float* Cf = reinterpret_cast<float*>(Cv);
                float2 r0 = *reinterpret_cast<const float2*>(res + o0);
                float2 r1 = *reinterpret_cast<const float2*>(res + o1);
                *reinterpret_cast<float2*>(Cf + o0) = make_float2(v00 + r0.x, v01 + r0.y);
                *reinterpret_cast<float2*>(Cf + o1) = make_float2(v10 + r1.x, v11 + r1.y);
            } else {
                __half* Ch = reinterpret_cast<__half*>(Cv);
                *reinterpret_cast<__half2*>(Ch + o0) = __floats2half2_rn(v00, v01);
                *reinterpret_cast<__half2*>(Ch + o1) = __floats2half2_rn(v10, v11);
            }
        }
    }
}

// ---------------- Flash attention: 128-row Q tile, fp16 mma, reg softmax
// Q,K,V fp16 (row stride LDA3). O fp16 (stride DD). 256 threads, 8 warps.
template<bool CAUSAL>
__global__ __launch_bounds__(256, 3)
void attn_h(const __half* __restrict__ Q,
            const __half* __restrict__ K,
            const __half* __restrict__ V,
            __half* __restrict__ O,
            int SKV)
{
    extern __shared__ char smraw[];
    __half* Qs = reinterpret_cast<__half*>(smraw);      // 128 rows
    __half* Ks = Qs + 128 * AH;                         // 64 rows
    __half* Vs = Ks + 64 * AH;                          // 64 rows

    const int t = threadIdx.x;
    const int wid = t >> 5, lane = t & 31;
    const int g = lane >> 2, tig = lane & 3;
    const int wm = wid * 16;                            // 0..112

    const int qt = CAUSAL ? ((int)gridDim.x - 1 - (int)blockIdx.x) : blockIdx.x;
    const int bh = blockIdx.y;
    const int b = bh / HH, h = bh % HH;
    const int q0 = qt * 128;

    size_t qbase  = ((size_t)b * TT + q0) * LDA3 + h * HD;
    size_t kvbase = (size_t)b * SKV * LDA3 + h * HD;
    uint32_t sQs = s2u(Qs), sKs = s2u(Ks), sVs = s2u(Vs);

    const int laneq = lane >> 3;
    const int lrow8 = lane & 7;
    const int aoffA = (wm + lrow8 + (laneq & 1) * 8) * AH + (laneq >> 1) * 8;
    const int boffK = (lrow8 + (laneq >> 1) * 8) * AH + (laneq & 1) * 8;
    const uint32_t vlaneoff = (uint32_t)((lrow8 + 8 * (laneq & 1)) * AH * 2 + (laneq >> 1) * 16);

    // load Q tile (128 x 64 halves): 1024 chunks over 256 threads
    #pragma unroll
    for (int c = 0; c < 4; c++) {
        int idx = c * 256 + t;
        int row = idx >> 3, seg = idx & 7;
        *reinterpret_cast<uint4*>(&Qs[row * AH + seg * 8]) =
            *reinterpret_cast<const uint4*>(Q + qbase + (size_t)row * LDA3 + seg * 8);
    }

    float m0 = -3.0e38f, m1 = -3.0e38f, l0 = 0.f, l1 = 0.f;

    float o[8][4];
    #pragma unroll
    for (int fj = 0; fj < 8; fj++)
        #pragma unroll
        for (int r = 0; r < 4; r++) o[fj][r] = 0.f;

    const int ktEnd = CAUSAL ? (2 * qt + 1) : (SKV / 64 - 1);

    for (int kt = 0; kt <= ktEnd; kt++) {
        const int k0g = kt * 64;
        // load K/V tiles: 512 chunks each over 256 threads
        #pragma unroll
        for (int c = 0; c < 2; c++) {
            int idx = c * 256 + t;
            int row = idx >> 3, seg = idx & 7;
            cp16(sKs + (row * AH + seg * 8) * 2, K + kvbase + (size_t)(k0g + row) * LDA3 + seg * 8);
            cp16(sVs + (row * AH + seg * 8) * 2, V + kvbase + (size_t)(k0g + row) * LDA3 + seg * 8);
        }
        cp_commit();
        cp_wait<0>();
        __syncthreads();

        float cS[8][4];
        #pragma unroll
        for (int fj = 0; fj < 8; fj++)
            #pragma unroll
            for (int r = 0; r < 4; r++) cS[fj][r] = 0.f;

        #pragma unroll
        for (int k0 = 0; k0 < 64; k0 += 16) {
            uint32_t a[4];
            LDM4(a[0], a[1], a[2], a[3], sQs + (uint32_t)((aoffA + k0) * 2));
            #pragma unroll
            for (int p = 0; p < 4; p++) {
                uint32_t r0, r1, r2, r3;
                LDM4(r0, r1, r2, r3,
                     sKs + (uint32_t)((boffK + p * 16 * AH + k0) * 2));
                uint32_t b0[2] = { r0, r1 };
                uint32_t b1[2] = { r2, r3 };
                mma16(cS[2*p],     a, b0);
                mma16(cS[2*p + 1], a, b1);
            }
        }

        // causal mask on the two diagonal-overlap tiles (global compare)
        if (CAUSAL && kt >= 2 * qt) {
            int rg0 = q0 + wm + g, rg1 = rg0 + 8;
            #pragma unroll
            for (int fj = 0; fj < 8; fj++) {
                int cg = k0g + 8 * fj + 2 * tig;
                if (cg     > rg0) cS[fj][0] = -1.0e30f;
                if (cg + 1 > rg0) cS[fj][1] = -1.0e30f;
                if (cg     > rg1) cS[fj][2] = -1.0e30f;
                if (cg + 1 > rg1) cS[fj][3] = -1.0e30f;
            }
        }

        float mx0 = -3.0e38f, mx1 = -3.0e38f;
        #pragma unroll
        for (int fj = 0; fj < 8; fj++) {
            mx0 = fmaxf(mx0, fmaxf(cS[fj][0], cS[fj][1]));
            mx1 = fmaxf(mx1, fmaxf(cS[fj][2], cS[fj][3]));
        }
        mx0 = fmaxf(mx0, __shfl_xor_sync(0xffffffffu, mx0, 1));
        mx0 = fmaxf(mx0, __shfl_xor_sync(0xffffffffu, mx0, 2));
        mx1 = fmaxf(mx1, __shfl_xor_sync(0xffffffffu, mx1, 1));
        mx1 = fmaxf(mx1, __shfl_xor_sync(0xffffffffu, mx1, 2));

        float nm0 = fmaxf(m0, mx0), nm1 = fmaxf(m1, mx1);
        float fac0 = __expf(0.125f * (m0 - nm0));
        float fac1 = __expf(0.125f * (m1 - nm1));

        uint32_t pg[8], pg8[8];
        float s0 = 0.f, s1 = 0.f;
        #pragma unroll
        for (int fj = 0; fj < 8; fj++) {
            __half h00 = __float2half_rn(__expf(0.125f * (cS[fj][0] - nm0)));
            __half h01 = __float2half_rn(__expf(0.125f * (cS[fj][1] - nm0)));
            __half h10 = __float2half_rn(__expf(0.125f * (cS[fj][2] - nm1)));
            __half h11 = __float2half_rn(__expf(0.125f * (cS[fj][3] - nm1)));
            __half2 p0 = __halves2half2(h00, h01);
            __half2 p1 = __halves2half2(h10, h11);
            pg[fj]  = *reinterpret_cast<uint32_t*>(&p0);
            pg8[fj] = *reinterpret_cast<uint32_t*>(&p1);
            s0 += __half2float(h00) + __half2float(h01);
            s1 += __half2float(h10) + __half2float(h11);
        }
        s0 += __shfl_xor_sync(0xffffffffu, s0, 1);
        s0 += __shfl_xor_sync(0xffffffffu, s0, 2);
        s1 += __shfl_xor_sync(0xffffffffu, s1, 1);
        s1 += __shfl_xor_sync(0xffffffffu, s1, 2);

        l0 = l0 * fac0 + s0;
        l1 = l1 * fac1 + s1;
        m0 = nm0; m1 = nm1;

        #pragma unroll
        for (int fj = 0; fj < 8; fj++) {
            o[fj][0] *= fac0; o[fj][1] *= fac0;
            o[fj][2] *= fac1; o[fj][3] *= fac1;
        }
        #pragma unroll
        for (int kb = 0; kb < 4; kb++) {
            uint32_t a[4];
            a[0] = pg [2*kb];
            a[1] = pg8[2*kb];
            a[2] = pg [2*kb + 1];
            a[3] = pg8[2*kb + 1];
            #pragma unroll
            for (int p = 0; p < 4; p++) {
                uint32_t r0, r1, r2, r3;
                LDM4T(r0, r1, r2, r3,
                      sVs + vlaneoff + (uint32_t)(kb * 16 * AH * 2 + p * 32));
                uint32_t b0[2] = { r0, r1 };
                uint32_t b1[2] = { r2, r3 };
                mma16(o[2*p],     a, b0);
                mma16(o[2*p + 1], a, b1);
            }
        }
        __syncthreads();
    }

    float inv_lo = 1.0f / l0;
    float inv_hi = 1.0f / l1;
    #pragma unroll
    for (int fj = 0; fj < 8; fj++) {
        int colL = 8 * fj + 2 * tig;
        size_t off0 = ((size_t)b * TT + q0 + wm + g) * DD + h * HD + colL;
        size_t off1 = ((size_t)b * TT + q0 + wm + g + 8) * DD + h * HD + colL;
        *reinterpret_cast<__half2*>(O + off0) =
            __floats2half2_rn(o[fj][0] * inv_lo, o[fj][1] * inv_lo);
        *reinterpret_cast<__half2*>(O + off1) =
            __floats2half2_rn(o[fj][2] * inv_hi, o[fj][3] * inv_hi);
    }
}

// ---------------- launch ----------------
extern "C" void kernel_launch(void* const* d_in, const int* in_sizes, int n_in,
                              void* d_out, int out_size)
{
    const float* tgt  = (const float*)d_in[0];
    const float* enc  = (const float*)d_in[1];
    const float* s_wq = (const float*)d_in[4];
    const float* s_wk = (const float*)d_in[5];
    const float* s_wv = (const float*)d_in[6];
    const float* s_wo = (const float*)d_in[7];
    const float* s_bq = (const float*)d_in[8];
    const float* s_bk = (const float*)d_in[9];
    const float* s_bv = (const float*)d_in[10];
    const float* s_bo = (const float*)d_in[11];
    const float* c_wq = (const float*)d_in[12];
    const float* c_wk = (const float*)d_in[13];
    const float* c_wv = (const float*)d_in[14];
    const float* c_wo = (const float*)d_in[15];
    const float* c_bq = (const float*)d_in[16];
    const float* c_bk = (const float*)d_in[17];
    const float* c_bv = (const float*)d_in[18];
    const float* c_bo = (const float*)d_in[19];
    const float* f_w1 = (const float*)d_in[20];
    const float* f_b1 = (const float*)d_in[21];
    const float* f_w2 = (const float*)d_in[22];
    const float* f_b2 = (const float*)d_in[23];
    const float* ln1g = (const float*)d_in[24];
    const float* ln1b = (const float*)d_in[25];
    const float* ln2g = (const float*)d_in[26];
    const float* ln2b = (const float*)d_in[27];
    const float* ln3g = (const float*)d_in[28];
    const float* ln3b = (const float*)d_in[29];
    float* out = (float*)d_out;

    float *X, *B3, *B2;
    __half *LN, *QKV, *CTX, *FFb, *WT, *ENC;
    cudaGetSymbolAddress((void**)&X,   g_X);
    cudaGetSymbolAddress((void**)&LN,  g_LN);
    cudaGetSymbolAddress((void**)&QKV, g_QKV);
    cudaGetSymbolAddress((void**)&CTX, g_CTX);
    cudaGetSymbolAddress((void**)&FFb, g_FF);
    cudaGetSymbolAddress((void**)&WT,  g_WT);
    cudaGetSymbolAddress((void**)&ENC, g_ENC);
    cudaGetSymbolAddress((void**)&B3,  g_B3);
    cudaGetSymbolAddress((void**)&B2,  g_B2);

    const size_t M1 = 1024 * 1024;
    __half* WTs3  = WT + 0*M1;   // s_wq|s_wk|s_wv
    __half* WTswo = WT + 3*M1;
    __half* WTcwq = WT + 4*M1;
    __half* WTc2  = WT + 5*M1;   // c_wk|c_wv
    __half* WTcwo = WT + 7*M1;
    __half* WTf1  = WT + 8*M1;
    __half* WTf2  = WT + 12*M1;

    cudaFuncSetAttribute(attn_h<true>,  cudaFuncAttributeMaxDynamicSharedMemorySize, ATTN_SMEM);
    cudaFuncSetAttribute(attn_h<false>, cudaFuncAttributeMaxDynamicSharedMemorySize, ATTN_SMEM);
    cudaFuncSetAttribute(gemm_h<1>, cudaFuncAttributeMaxDynamicSharedMemorySize, GEMM_SMEM);
    cudaFuncSetAttribute(gemm_h<2>, cudaFuncAttributeMaxDynamicSharedMemorySize, GEMM_SMEM);
    cudaFuncSetAttribute(gemm_h<4>, cudaFuncAttributeMaxDynamicSharedMemorySize, GEMM_SMEM);

    // ---- batched weight transpose + enc copy (one launch), bias concat ----
    TransArgs ta;
    ta.s[0] = s_wq; ta.d[0] = WTs3 + 0*M1;
    ta.s[1] = s_wk; ta.d[1] = WTs3 + 1*M1;
    ta.s[2] = s_wv; ta.d[2] = WTs3 + 2*M1;
    ta.s[3] = s_wo; ta.d[3] = WTswo;
    ta.s[4] = c_wq; ta.d[4] = WTcwq;
    ta.s[5] = c_wk; ta.d[5] = WTc2 + 0*M1;
    ta.s[6] = c_wv; ta.d[6] = WTc2 + 1*M1;
    ta.s[7] = c_wo; ta.d[7] = WTcwo;
    ta.s[8] = f_w1; ta.d[8] = WTf1;
    ta.s[9] = f_w2; ta.d[9] = WTf2;
    ta.enc = enc;  ta.encd = ENC;
    transpose_all<<<20480, dim3(32, 8)>>>(ta);
    cudaMemcpyAsync(B3,        s_bq, DD*4, cudaMemcpyDeviceToDevice, 0);
    cudaMemcpyAsync(B3 + 1024, s_bk, DD*4, cudaMemcpyDeviceToDevice, 0);
    cudaMemcpyAsync(B3 + 2048, s_bv, DD*4, cudaMemcpyDeviceToDevice, 0);
    cudaMemcpyAsync(B2,        c_bk, DD*4, cudaMemcpyDeviceToDevice, 0);
    cudaMemcpyAsync(B2 + 1024, c_bv, DD*4, cudaMemcpyDeviceToDevice, 0);

    dim3 blk(256);
    dim3 ablk(256);
    dim3 gQKV(LDA3 / BN, NROWS / BM);   // (24, 32)
    dim3 gKV (2048 / BN, NROWS / BM);   // (16, 32)
    dim3 gPrj(DD / BN,   NROWS / BM);   // (8, 32)
    dim3 gFF1(FFD / BN,  NROWS / BM);   // (32, 32)
    dim3 gAttn(TT / 128, BB * HH);      // (8, 64)

    // ---- self-attention block ----
    ln_kernel<<<NROWS, 256>>>(tgt, ln1g, ln1b, LN);
    gemm_h<4><<<gQKV, blk, GEMM_SMEM>>>(LN, WTs3, B3, nullptr, QKV, DD, LDA3, LDA3);
    attn_h<true><<<gAttn, ablk, ATTN_SMEM>>>(QKV, QKV + 1024, QKV + 2048, CTX, TT);
    gemm_h<2><<<gPrj, blk, GEMM_SMEM>>>(CTX, WTswo, s_bo, tgt, X, DD, DD, DD);

    // ---- cross-attention block ----
    ln_kernel<<<NROWS, 256>>>(X, ln2g, ln2b, LN);
    gemm_h<4><<<gPrj, blk, GEMM_SMEM>>>(LN,  WTcwq, c_bq, nullptr, QKV, DD, DD, LDA3);
    gemm_h<4><<<gKV,  blk, GEMM_SMEM>>>(ENC, WTc2,  B2,  nullptr, QKV + 1024, DD, 2048, LDA3);
    attn_h<false><<<gAttn, ablk, ATTN_SMEM>>>(QKV, QKV + 1024, QKV + 2048, CTX, SS);
    gemm_h<2><<<gPrj, blk, GEMM_SMEM>>>(CTX, WTcwo, c_bo, X, X, DD, DD, DD);

    // ---- FFN block ----
    ln_kernel<<<NROWS, 256>>>(X, ln3g, ln3b, LN);
    gemm_h<1><<<gFF1, blk, GEMM_SMEM>>>(LN, WTf1, f_b1, nullptr, FFb, DD, FFD, FFD);
    gemm_h<2><<<gPrj, blk, GEMM_SMEM>>>(FFb, WTf2, f_b2, X, out, FFD, DD, DD);
}

// round 13
// speedup vs baseline: 1.0248x; 1.0248x over previous
#include <cuda_runtime.h>
#include <cuda_fp16.h>
#include <cstdint>

// Problem constants (fixed by setup_inputs)
#define BB 4
#define TT 1024
#define SS 1024
#define DD 1024
#define HH 16
#define HD 64
#define FFD 4096
#define NROWS (BB*TT)   // 4096
#define LDA3 3072       // fused QKV row stride (halves)

// GEMM tiling (mma.sync fp16, m16n8k16): 128x128 CTA tile, 64x32 warp tile
#define BM 128
#define BN 128
#define BKH 64                        // K halves per stage chunk
#define ROWH 72                       // smem row stride in halves (64 + 8 pad)
#define STAGE_H (2 * BM * ROWH)       // halves per stage (A + B tiles)
#define GEMM_SMEM (3 * STAGE_H * 2)   // 110592 bytes

// Attention (fp16 mma) smem: Q, K, V tiles only (register softmax)
#define AH 72                         // half row stride
#define ATTN_SMEM (3*64*AH*2)         // 27648 bytes

// ---------------- scratch (device globals; no allocation) ----------------
__device__ float  g_X  [NROWS*DD];
__device__ __half g_LN [NROWS*DD];
__device__ __half g_QKV[NROWS*LDA3];     // fused Q|K|V (self and cross), fp16
__device__ __half g_CTX[NROWS*DD];
__device__ __half g_FF [NROWS*FFD];
__device__ __half g_WT [16*1024*1024];   // transposed fp16 weights
__device__ __half g_ENC[BB*SS*DD];       // fp16 encoder activations
__device__ float  g_B3 [3072];           // concat self q|k|v bias
__device__ float  g_B2 [2048];           // concat cross k|v bias

// ---------------- helpers ----------------
__device__ __forceinline__ uint32_t s2u(const void* p) {
    uint32_t a;
    asm("{ .reg .u64 t; cvta.to.shared.u64 t, %1; cvt.u32.u64 %0, t; }" : "=r"(a) : "l"(p));
    return a;
}
__device__ __forceinline__ void cp16(uint32_t dst, const void* src) {
    asm volatile("cp.async.cg.shared.global [%0], [%1], 16;" :: "r"(dst), "l"(src));
}
__device__ __forceinline__ void cp_commit() { asm volatile("cp.async.commit_group;" ::: "memory"); }
template<int N> __device__ __forceinline__ void cp_wait() {
    asm volatile("cp.async.wait_group %0;" :: "n"(N) : "memory");
}
__device__ __forceinline__ void mma16(float* c, const uint32_t* a, const uint32_t* b) {
    asm volatile(
        "mma.sync.aligned.m16n8k16.row.col.f32.f16.f16.f32 "
        "{%0,%1,%2,%3}, {%4,%5,%6,%7}, {%8,%9}, {%0,%1,%2,%3};"
        : "+f"(c[0]), "+f"(c[1]), "+f"(c[2]), "+f"(c[3])
        : "r"(a[0]), "r"(a[1]), "r"(a[2]), "r"(a[3]), "r"(b[0]), "r"(b[1]));
}
#define LDM4(r0, r1, r2, r3, addr) \
    asm volatile("ldmatrix.sync.aligned.m8n8.x4.shared.b16 {%0,%1,%2,%3}, [%4];" \
        : "=r"(r0), "=r"(r1), "=r"(r2), "=r"(r3) : "r"(addr))
#define LDM4T(r0, r1, r2, r3, addr) \
    asm volatile("ldmatrix.sync.aligned.m8n8.x4.trans.shared.b16 {%0,%1,%2,%3}, [%4];" \
        : "=r"(r0), "=r"(r1), "=r"(r2), "=r"(r3) : "r"(addr))

// ---------------- batched transpose + fp16 round + enc copy ----------------
struct TransArgs {
    const float* s[10];
    __half* d[10];
    const float* enc;
    __half* encd;
};
__global__ void transpose_all(TransArgs ta)
{
    __shared__ float tile[32][33];
    int bid = blockIdx.x;
    int tx = threadIdx.x, ty = threadIdx.y;
    if (bid >= 16384) {
        int i = (bid - 16384) * 256 + ty * 32 + tx;
        float4 v = reinterpret_cast<const float4*>(ta.enc)[i];
        reinterpret_cast<__half2*>(ta.encd)[2*i]   = __floats2half2_rn(v.x, v.y);
        reinterpret_cast<__half2*>(ta.encd)[2*i+1] = __floats2half2_rn(v.z, v.w);
        return;
    }
    const float* src; __half* dst; int R, C, bx, by;
    if (bid < 8192) {
        int w = bid >> 10, tt = bid & 1023;
        src = ta.s[w]; dst = ta.d[w]; R = 1024; C = 1024;
        bx = (tt & 31) * 32; by = (tt >> 5) * 32;
    } else if (bid < 12288) {
        int tt = bid - 8192;
        src = ta.s[8]; dst = ta.d[8]; R = 1024; C = 4096;
        bx = (tt & 127) * 32; by = (tt >> 7) * 32;
    } else {
        int tt = bid - 12288;
        src = ta.s[9]; dst = ta.d[9]; R = 4096; C = 1024;
        bx = (tt & 31) * 32; by = (tt >> 5) * 32;
    }
    #pragma unroll
    for (int j = 0; j < 32; j += 8)
        tile[ty + j][tx] = src[(size_t)(by + ty + j) * C + bx + tx];
    __syncthreads();
    #pragma unroll
    for (int j = 0; j < 32; j += 8)
        dst[(size_t)(bx + ty + j) * R + by + tx] = __float2half_rn(tile[tx][ty + j]);
}

// ---------------- LayerNorm (fp32 in, fp16 out; feeds GEMMs only) -------
__global__ void ln_kernel(const float* __restrict__ x,
                          const float* __restrict__ g,
                          const float* __restrict__ b,
                          __half* __restrict__ y)
{
    int row = blockIdx.x;
    int t = threadIdx.x;
    const float4* xr = reinterpret_cast<const float4*>(x + (size_t)row * DD);
    float4 v = xr[t];
    float s  = v.x + v.y + v.z + v.w;
    float ss = v.x*v.x + v.y*v.y + v.z*v.z + v.w*v.w;
    #pragma unroll
    for (int o = 16; o > 0; o >>= 1) {
        s  += __shfl_xor_sync(0xffffffffu, s,  o);
        ss += __shfl_xor_sync(0xffffffffu, ss, o);
    }
    __shared__ float ws[8], wss[8];
    __shared__ float s_mu, s_rstd;
    int lane = t & 31, wid = t >> 5;
    if (lane == 0) { ws[wid] = s; wss[wid] = ss; }
    __syncthreads();
    if (t == 0) {
        float S = 0.f, SS2 = 0.f;
        #pragma unroll
        for (int i = 0; i < 8; i++) { S += ws[i]; SS2 += wss[i]; }
        float mu = S * (1.0f / DD);
        float var = SS2 * (1.0f / DD) - mu * mu;
        s_mu = mu;
        s_rstd = rsqrtf(var + 1e-5f);
    }
    __syncthreads();
    float mu = s_mu, rstd = s_rstd;
    float4 gg = reinterpret_cast<const float4*>(g)[t];
    float4 bb = reinterpret_cast<const float4*>(b)[t];
    __half2* yr = reinterpret_cast<__half2*>(y + (size_t)row * DD);
    yr[2*t]   = __floats2half2_rn((v.x - mu) * rstd * gg.x + bb.x,
                                  (v.y - mu) * rstd * gg.y + bb.y);
    yr[2*t+1] = __floats2half2_rn((v.z - mu) * rstd * gg.z + bb.z,
                                  (v.w - mu) * rstd * gg.w + bb.w);
}

// ---------------- fp16 mma.sync GEMM (ldmatrix + interleaved prefetch) --
// C[Nrows, Mout] = A[Nrows, K] @ WT[Mout, K]^T + bias (+relu / +res)
// EPI: 1 = bias+relu -> half, 2 = bias+residual -> float, 4 = bias -> half
template<int EPI>
__global__ __launch_bounds__(256, 2)
void gemm_h(const __half* __restrict__ A, const __half* __restrict__ WT,
            const float* __restrict__ bias, const float* __restrict__ res,
            void* __restrict__ Cv, int K, int Mout, int ldc)
{
    extern __shared__ __half smh[];
    const int t = threadIdx.x;
    const int wid = t >> 5, lane = t & 31;
    const int g = lane >> 2, tig = lane & 3;
    const int wm = (wid & 1) * 64;
    const int wn = (wid >> 1) * 32;
    const int n0 = blockIdx.y * BM;
    const int m0 = blockIdx.x * BN;

    const __half* Ab = A  + (size_t)n0 * K;
    const __half* Bb = WT + (size_t)m0 * K;

    const int ldrow = t >> 1;
    const int ldseg = (t & 1) * 32;

    const int laneq = lane >> 3;
    const int lrow8 = lane & 7;
    const int aoff0 = (wm + lrow8 + (laneq & 1) * 8) * ROWH + (laneq >> 1) * 8;
    const int boff0 = BM * ROWH + (wn + lrow8 + (laneq >> 1) * 8) * ROWH + (laneq & 1) * 8;

    float c[4][4][4];
    #pragma unroll
    for (int i = 0; i < 4; i++)
        #pragma unroll
        for (int j = 0; j < 4; j++)
            #pragma unroll
            for (int r = 0; r < 4; r++) c[i][j][r] = 0.f;

    const int NIter = K / BKH;
    uint32_t smbase = s2u(smh);

    #pragma unroll
    for (int p = 0; p < 2; p++) {
        uint32_t sA = smbase + p * STAGE_H * 2;
        uint32_t sB = sA + BM * ROWH * 2;
        const __half* Ak = Ab + p * BKH;
        const __half* Bk = Bb + p * BKH;
        #pragma unroll
        for (int q = 0; q < 2; q++) {
            int seg = ldseg + q * 16;
            cp16(sA + (ldrow * ROWH + seg) * 2,      Ak + (size_t)ldrow * K + seg);
            cp16(sA + (ldrow * ROWH + seg + 8) * 2,  Ak + (size_t)ldrow * K + seg + 8);
            cp16(sB + (ldrow * ROWH + seg) * 2,      Bk + (size_t)ldrow * K + seg);
            cp16(sB + (ldrow * ROWH + seg + 8) * 2,  Bk + (size_t)ldrow * K + seg + 8);
        }
        cp_commit();
    }

    for (int i = 0; i < NIter; i++) {
        cp_wait<1>();
        __syncthreads();

        uint32_t stg = smbase + (uint32_t)((i % 3) * STAGE_H * 2);

        // ks = 0 compute
        {
            uint32_t a[4][4], b[4][2];
            uint32_t aaddr = stg + (uint32_t)(aoff0 * 2);
            #pragma unroll
            for (int fi = 0; fi < 4; fi++)
                LDM4(a[fi][0], a[fi][1], a[fi][2], a[fi][3],
                     aaddr + (uint32_t)(fi * 16 * ROWH * 2));
            uint32_t baddr = stg + (uint32_t)(boff0 * 2);
            #pragma unroll
            for (int p = 0; p < 2; p++) {
                uint32_t r0, r1, r2, r3;
                LDM4(r0, r1, r2, r3, baddr + (uint32_t)(p * 16 * ROWH * 2));
                b[2*p][0] = r0;   b[2*p][1] = r1;
                b[2*p+1][0] = r2; b[2*p+1][1] = r3;
            }
            #pragma unroll
            for (int fi = 0; fi < 4; fi++)
                #pragma unroll
                for (int fj = 0; fj < 4; fj++)
                    mma16(c[fi][fj], a[fi], b[fj]);
        }

        // issue prefetch for i+2
        int ip = i + 2;
        if (ip < NIter) {
            int s = ip % 3;
            uint32_t sA = smbase + s * STAGE_H * 2;
            uint32_t sB = sA + BM * ROWH * 2;
            const __half* Ak = Ab + ip * BKH;
            const __half* Bk = Bb + ip * BKH;
            #pragma unroll
            for (int q = 0; q < 2; q++) {
                int seg = ldseg + q * 16;
                cp16(sA + (ldrow * ROWH + seg) * 2,      Ak + (size_t)ldrow * K + seg);
                cp16(sA + (ldrow * ROWH + seg + 8) * 2,  Ak + (size_t)ldrow * K + seg + 8);
                cp16(sB + (ldrow * ROWH + seg) * 2,      Bk + (size_t)ldrow * K + seg);
                cp16(sB + (ldrow * ROWH + seg + 8) * 2,  Bk + (size_t)ldrow * K + seg + 8);
            }
        }
        cp_commit();

        // ks = 1..3 compute
        #pragma unroll
        for (int ks = 1; ks < 4; ks++) {
            uint32_t a[4][4], b[4][2];
            uint32_t aaddr = stg + (uint32_t)((aoff0 + ks * 16) * 2);
            #pragma unroll
            for (int fi = 0; fi < 4; fi++)
                LDM4(a[fi][0], a[fi][1], a[fi][2], a[fi][3],
                     aaddr + (uint32_t)(fi * 16 * ROWH * 2));
            uint32_t baddr = stg + (uint32_t)((boff0 + ks * 16) * 2);
            #pragma unroll
            for (int p = 0; p < 2; p++) {
                uint32_t r0, r1, r2, r3;
                LDM4(r0, r1, r2, r3, baddr + (uint32_t)(p * 16 * ROWH * 2));
                b[2*p][0] = r0;   b[2*p][1] = r1;
                b[2*p+1][0] = r2; b[2*p+1][1] = r3;
            }
            #pragma unroll
            for (int fi = 0; fi < 4; fi++)
                #pragma unroll
                for (int fj = 0; fj < 4; fj++)
                    mma16(c[fi][fj], a[fi], b[fj]);
        }
    }

    #pragma unroll
    for (int fi = 0; fi < 4; fi++) {
        #pragma unroll
        for (int fj = 0; fj < 4; fj++) {
            int row = n0 + wm + 16 * fi + g;
            int col = m0 + wn + 8 * fj + 2 * tig;
            float b0 = __ldg(bias + col), b1 = __ldg(bias + col + 1);
            float v00 = c[fi][fj][0] + b0, v01 = c[fi][fj][1] + b1;
            float v10 = c[fi][fj][2] + b0, v11 = c[fi][fj][3] + b1;
            size_t o0 = (size_t)row * ldc + col;
            size_t o1 = (size_t)(row + 8) * ldc + col;
            if (EPI == 1) {
                __half* Ch = reinterpret_cast<__half*>(Cv);
                *reinterpret_cast<__half2*>(Ch + o0) =
                    __floats2half2_rn(fmaxf(v00, 0.f), fmaxf(v01, 0.f));
                *reinterpret_cast<__half2*>(Ch + o1) =
                    __floats2half2_rn(fmaxf(v10, 0.f), fmaxf(v11, 0.f));
            } else if (EPI == 2) {
                float* Cf = reinterpret_cast<float*>(Cv);
                float2 r0 = *reinterpret_cast<const float2*>(res + o0);
                float2 r1 = *reinterpret_cast<const float2*>(res + o1);
                *reinterpret_cast<float2*>(Cf + o0) = make_float2(v00 + r0.x, v01 + r0.y);
                *reinterpret_cast<float2*>(Cf + o1) = make_float2(v10 + r1.x, v11 + r1.y);
            } else {
                __half* Ch = reinterpret_cast<__half*>(Cv);
                *reinterpret_cast<__half2*>(Ch + o0) = __floats2half2_rn(v00, v01);
                *reinterpret_cast<__half2*>(Ch + o1) = __floats2half2_rn(v10, v11);
            }
        }
    }
}

// ---------------- Flash attention, fp16 mma + register softmax (h2exp2) -
template<bool CAUSAL>
__global__ __launch_bounds__(128, 6)
void attn_h(const __half* __restrict__ Q,
            const __half* __restrict__ K,
            const __half* __restrict__ V,
            __half* __restrict__ O,
            int SKV)
{
    extern __shared__ char smraw[];
    __half* Qs = reinterpret_cast<__half*>(smraw);
    __half* Ks = Qs + 64 * AH;
    __half* Vs = Ks + 64 * AH;

    const int t = threadIdx.x;
    const int wid = t >> 5, lane = t & 31;
    const int g = lane >> 2, tig = lane & 3;
    const int wm = wid * 16;

    const int qt = CAUSAL ? ((int)gridDim.x - 1 - (int)blockIdx.x) : blockIdx.x;
    const int bh = blockIdx.y;
    const int b = bh / HH, h = bh % HH;
    const int q0 = qt * 64;

    size_t qbase  = ((size_t)b * TT + q0) * LDA3 + h * HD;
    size_t kvbase = (size_t)b * SKV * LDA3 + h * HD;
    uint32_t sQs = s2u(Qs), sKs = s2u(Ks), sVs = s2u(Vs);

    const int laneq = lane >> 3;
    const int lrow8 = lane & 7;
    const int aoffA = (wm + lrow8 + (laneq & 1) * 8) * AH + (laneq >> 1) * 8;
    const int boffK = (lrow8 + (laneq >> 1) * 8) * AH + (laneq & 1) * 8;
    const uint32_t vlaneoff = (uint32_t)((lrow8 + 8 * (laneq & 1)) * AH * 2 + (laneq >> 1) * 16);

    #pragma unroll
    for (int c = 0; c < 4; c++) {
        int idx = c * 128 + t;
        int row = idx >> 3, seg = idx & 7;
        *reinterpret_cast<uint4*>(&Qs[row * AH + seg * 8]) =
            *reinterpret_cast<const uint4*>(Q + qbase + (size_t)row * LDA3 + seg * 8);
    }

    float m0 = -3.0e38f, m1 = -3.0e38f, l0 = 0.f, l1 = 0.f;

    float o[8][4];
    #pragma unroll
    for (int fj = 0; fj < 8; fj++)
        #pragma unroll
        for (int r = 0; r < 4; r++) o[fj][r] = 0.f;

    const int ktEnd = CAUSAL ? qt : (SKV / 64 - 1);
    const float CEXP = 0.180336880111124f;   // 0.125 * log2(e)

    for (int kt = 0; kt <= ktEnd; kt++) {
        const int k0g = kt * 64;
        #pragma unroll
        for (int c = 0; c < 4; c++) {
            int idx = c * 128 + t;
            int row = idx >> 3, seg = idx & 7;
            cp16(sKs + (row * AH + seg * 8) * 2, K + kvbase + (size_t)(k0g + row) * LDA3 + seg * 8);
            cp16(sVs + (row * AH + seg * 8) * 2, V + kvbase + (size_t)(k0g + row) * LDA3 + seg * 8);
        }
        cp_commit();
        cp_wait<0>();
        __syncthreads();

        float cS[8][4];
        #pragma unroll
        for (int fj = 0; fj < 8; fj++)
            #pragma unroll
            for (int r = 0; r < 4; r++) cS[fj][r] = 0.f;

        #pragma unroll
        for (int k0 = 0; k0 < 64; k0 += 16) {
            uint32_t a[4];
            LDM4(a[0], a[1], a[2], a[3], sQs + (uint32_t)((aoffA + k0) * 2));
            #pragma unroll
            for (int p = 0; p < 4; p++) {
                uint32_t r0, r1, r2, r3;
                LDM4(r0, r1, r2, r3,
                     sKs + (uint32_t)((boffK + p * 16 * AH + k0) * 2));
                uint32_t b0[2] = { r0, r1 };
                uint32_t b1[2] = { r2, r3 };
                mma16(cS[2*p],     a, b0);
                mma16(cS[2*p + 1], a, b1);
            }
        }

        if (CAUSAL && kt == qt) {
            #pragma unroll
            for (int fj = 0; fj < 8; fj++) {
                int colL = 8 * fj + 2 * tig;
                int r0 = wm + g, r1 = wm + g + 8;
                if (colL     > r0) cS[fj][0] = -1.0e30f;
                if (colL + 1 > r0) cS[fj][1] = -1.0e30f;
                if (colL     > r1) cS[fj][2] = -1.0e30f;
                if (colL + 1 > r1) cS[fj][3] = -1.0e30f;
            }
        }

        float mx0 = -3.0e38f, mx1 = -3.0e38f;
        #pragma unroll
        for (int fj = 0; fj < 8; fj++) {
            mx0 = fmaxf(mx0, fmaxf(cS[fj][0], cS[fj][1]));
            mx1 = fmaxf(mx1, fmaxf(cS[fj][2], cS[fj][3]));
        }
        mx0 = fmaxf(mx0, __shfl_xor_sync(0xffffffffu, mx0, 1));
        mx0 = fmaxf(mx0, __shfl_xor_sync(0xffffffffu, mx0, 2));
        mx1 = fmaxf(mx1, __shfl_xor_sync(0xffffffffu, mx1, 1));
        mx1 = fmaxf(mx1, __shfl_xor_sync(0xffffffffu, mx1, 2));

        float nm0 = fmaxf(m0, mx0), nm1 = fmaxf(m1, mx1);
        float fac0 = __expf(0.125f * (m0 - nm0));
        float fac1 = __expf(0.125f * (m1 - nm1));
        float nb0 = nm0 * CEXP, nb1 = nm1 * CEXP;

        uint32_t pg[8], pg8[8];
        float s0 = 0.f, s1 = 0.f;
        #pragma unroll
        for (int fj = 0; fj < 8; fj++) {
            // x = (cS - nm) * 0.125 * log2e, packed to fp16x2, exp2 in fp16x2
            __half2 x0 = __floats2half2_rn(fmaf(cS[fj][0], CEXP, -nb0),
                                           fmaf(cS[fj][1], CEXP, -nb0));
            __half2 x1 = __floats2half2_rn(fmaf(cS[fj][2], CEXP, -nb1),
                                           fmaf(cS[fj][3], CEXP, -nb1));
            __half2 p0 = h2exp2(x0);
            __half2 p1 = h2exp2(x1);
            pg[fj]  = *reinterpret_cast<uint32_t*>(&p0);
            pg8[fj] = *reinterpret_cast<uint32_t*>(&p1);
            float2 f0 = __half22float2(p0);
            float2 f1 = __half22float2(p1);
            s0 += f0.x + f0.y;
            s1 += f1.x + f1.y;
        }
        s0 += __shfl_xor_sync(0xffffffffu, s0, 1);
        s0 += __shfl_xor_sync(0xffffffffu, s0, 2);
        s1 += __shfl_xor_sync(0xffffffffu, s1, 1);
        s1 += __shfl_xor_sync(0xffffffffu, s1, 2);

        l0 = l0 * fac0 + s0;
        l1 = l1 * fac1 + s1;
        m0 = nm0; m1 = nm1;

        #pragma unroll
        for (int fj = 0; fj < 8; fj++) {
            o[fj][0] *= fac0; o[fj][1] *= fac0;
            o[fj][2] *= fac1; o[fj][3] *= fac1;
        }
        #pragma unroll
        for (int kb = 0; kb < 4; kb++) {
            uint32_t a[4];
            a[0] = pg [2*kb];
            a[1] = pg8[2*kb];
            a[2] = pg [2*kb + 1];
            a[3] = pg8[2*kb + 1];
            #pragma unroll
            for (int p = 0; p < 4; p++) {
                uint32_t r0, r1, r2, r3;
                LDM4T(r0, r1, r2, r3,
                      sVs + vlaneoff + (uint32_t)(kb * 16 * AH * 2 + p * 32));
                uint32_t b0[2] = { r0, r1 };
                uint32_t b1[2] = { r2, r3 };
                mma16(o[2*p],     a, b0);
                mma16(o[2*p + 1], a, b1);
            }
        }
        __syncthreads();
    }

    float inv_lo = 1.0f / l0;
    float inv_hi = 1.0f / l1;
    #pragma unroll
    for (int fj = 0; fj < 8; fj++) {
        int colL = 8 * fj + 2 * tig;
        size_t off0 = ((size_t)b * TT + q0 + wm + g) * DD + h * HD + colL;
        size_t off1 = ((size_t)b * TT + q0 + wm + g + 8) * DD + h * HD + colL;
        *reinterpret_cast<__half2*>(O + off0) =
            __floats2half2_rn(o[fj][0] * inv_lo, o[fj][1] * inv_lo);
        *reinterpret_cast<__half2*>(O + off1) =
            __floats2half2_rn(o[fj][2] * inv_hi, o[fj][3] * inv_hi);
    }
}

// ---------------- launch ----------------
extern "C" void kernel_launch(void* const* d_in, const int* in_sizes, int n_in,
                              void* d_out, int out_size)
{
    const float* tgt  = (const float*)d_in[0];
    const float* enc  = (const float*)d_in[1];
    const float* s_wq = (const float*)d_in[4];
    const float* s_wk = (const float*)d_in[5];
    const float* s_wv = (const float*)d_in[6];
    const float* s_wo = (const float*)d_in[7];
    const float* s_bq = (const float*)d_in[8];
    const float* s_bk = (const float*)d_in[9];
    const float* s_bv = (const float*)d_in[10];
    const float* s_bo = (const float*)d_in[11];
    const float* c_wq = (const float*)d_in[12];
    const float* c_wk = (const float*)d_in[13];
    const float* c_wv = (const float*)d_in[14];
    const float* c_wo = (const float*)d_in[15];
    const float* c_bq = (const float*)d_in[16];
    const float* c_bk = (const float*)d_in[17];
    const float* c_bv = (const float*)d_in[18];
    const float* c_bo = (const float*)d_in[19];
    const float* f_w1 = (const float*)d_in[20];
    const float* f_b1 = (const float*)d_in[21];
    const float* f_w2 = (const float*)d_in[22];
    const float* f_b2 = (const float*)d_in[23];
    const float* ln1g = (const float*)d_in[24];
    const float* ln1b = (const float*)d_in[25];
    const float* ln2g = (const float*)d_in[26];
    const float* ln2b = (const float*)d_in[27];
    const float* ln3g = (const float*)d_in[28];
    const float* ln3b = (const float*)d_in[29];
    float* out = (float*)d_out;

    float *X, *B3, *B2;
    __half *LN, *QKV, *CTX, *FFb, *WT, *ENC;
    cudaGetSymbolAddress((void**)&X,   g_X);
    cudaGetSymbolAddress((void**)&LN,  g_LN);
    cudaGetSymbolAddress((void**)&QKV, g_QKV);
    cudaGetSymbolAddress((void**)&CTX, g_CTX);
    cudaGetSymbolAddress((void**)&FFb, g_FF);
    cudaGetSymbolAddress((void**)&WT,  g_WT);
    cudaGetSymbolAddress((void**)&ENC, g_ENC);
    cudaGetSymbolAddress((void**)&B3,  g_B3);
    cudaGetSymbolAddress((void**)&B2,  g_B2);

    const size_t M1 = 1024 * 1024;
    __half* WTs3  = WT + 0*M1;   // s_wq|s_wk|s_wv
    __half* WTswo = WT + 3*M1;
    __half* WTcwq = WT + 4*M1;
    __half* WTc2  = WT + 5*M1;   // c_wk|c_wv
    __half* WTcwo = WT + 7*M1;
    __half* WTf1  = WT + 8*M1;
    __half* WTf2  = WT + 12*M1;

    cudaFuncSetAttribute(attn_h<true>,  cudaFuncAttributeMaxDynamicSharedMemorySize, ATTN_SMEM);
    cudaFuncSetAttribute(attn_h<false>, cudaFuncAttributeMaxDynamicSharedMemorySize, ATTN_SMEM);
    cudaFuncSetAttribute(gemm_h<1>, cudaFuncAttributeMaxDynamicSharedMemorySize, GEMM_SMEM);
    cudaFuncSetAttribute(gemm_h<2>, cudaFuncAttributeMaxDynamicSharedMemorySize, GEMM_SMEM);
    cudaFuncSetAttribute(gemm_h<4>, cudaFuncAttributeMaxDynamicSharedMemorySize, GEMM_SMEM);

    // ---- batched weight transpose + enc copy (one launch), bias concat ----
    TransArgs ta;
    ta.s[0] = s_wq; ta.d[0] = WTs3 + 0*M1;
    ta.s[1] = s_wk; ta.d[1] = WTs3 + 1*M1;
    ta.s[2] = s_wv; ta.d[2] = WTs3 + 2*M1;
    ta.s[3] = s_wo; ta.d[3] = WTswo;
    ta.s[4] = c_wq; ta.d[4] = WTcwq;
    ta.s[5] = c_wk; ta.d[5] = WTc2 + 0*M1;
    ta.s[6] = c_wv; ta.d[6] = WTc2 + 1*M1;
    ta.s[7] = c_wo; ta.d[7] = WTcwo;
    ta.s[8] = f_w1; ta.d[8] = WTf1;
    ta.s[9] = f_w2; ta.d[9] = WTf2;
    ta.enc = enc;  ta.encd = ENC;
    transpose_all<<<20480, dim3(32, 8)>>>(ta);
    cudaMemcpyAsync(B3,        s_bq, DD*4, cudaMemcpyDeviceToDevice, 0);
    cudaMemcpyAsync(B3 + 1024, s_bk, DD*4, cudaMemcpyDeviceToDevice, 0);
    cudaMemcpyAsync(B3 + 2048, s_bv, DD*4, cudaMemcpyDeviceToDevice, 0);
    cudaMemcpyAsync(B2,        c_bk, DD*4, cudaMemcpyDeviceToDevice, 0);
    cudaMemcpyAsync(B2 + 1024, c_bv, DD*4, cudaMemcpyDeviceToDevice, 0);

    dim3 blk(256);
    dim3 ablk(128);
    dim3 gQKV(LDA3 / BN, NROWS / BM);   // (24, 32)
    dim3 gKV (2048 / BN, NROWS / BM);   // (16, 32)
    dim3 gPrj(DD / BN,   NROWS / BM);   // (8, 32)
    dim3 gFF1(FFD / BN,  NROWS / BM);   // (32, 32)
    dim3 gAttn(TT / 64, BB * HH);       // (16, 64)

    // ---- self-attention block ----
    ln_kernel<<<NROWS, 256>>>(tgt, ln1g, ln1b, LN);
    gemm_h<4><<<gQKV, blk, GEMM_SMEM>>>(LN, WTs3, B3, nullptr, QKV, DD, LDA3, LDA3);
    attn_h<true><<<gAttn, ablk, ATTN_SMEM>>>(QKV, QKV + 1024, QKV + 2048, CTX, TT);
    gemm_h<2><<<gPrj, blk, GEMM_SMEM>>>(CTX, WTswo, s_bo, tgt, X, DD, DD, DD);

    // ---- cross-attention block ----
    ln_kernel<<<NROWS, 256>>>(X, ln2g, ln2b, LN);
    gemm_h<4><<<gPrj, blk, GEMM_SMEM>>>(LN,  WTcwq, c_bq, nullptr, QKV, DD, DD, LDA3);
    gemm_h<4><<<gKV,  blk, GEMM_SMEM>>>(ENC, WTc2,  B2,  nullptr, QKV + 1024, DD, 2048, LDA3);
    attn_h<false><<<gAttn, ablk, ATTN_SMEM>>>(QKV, QKV + 1024, QKV + 2048, CTX, SS);
    gemm_h<2><<<gPrj, blk, GEMM_SMEM>>>(CTX, WTcwo, c_bo, X, X, DD, DD, DD);

    // ---- FFN block ----
    ln_kernel<<<NROWS, 256>>>(X, ln3g, ln3b, LN);
    gemm_h<1><<<gFF1, blk, GEMM_SMEM>>>(LN, WTf1, f_b1, nullptr, FFb, DD, FFD, FFD);
    gemm_h<2><<<gPrj, blk, GEMM_SMEM>>>(FFb, WTf2, f_b2, X, out, FFD, DD, DD);
}

// round 14
// speedup vs baseline: 1.0613x; 1.0356x over previous
#include <cuda_runtime.h>
#include <cuda_fp16.h>
#include <cstdint>

// Problem constants (fixed by setup_inputs)
#define BB 4
#define TT 1024
#define SS 1024
#define DD 1024
#define HH 16
#define HD 64
#define FFD 4096
#define NROWS (BB*TT)   // 4096
#define LDA3 3072       // fused QKV row stride (halves)

// GEMM tiling (mma.sync fp16, m16n8k16): 128x128 CTA tile, 64x32 warp tile
#define BM 128
#define BN 128
#define BKH 64                        // K halves per stage chunk
#define ROWH 72                       // smem row stride in halves (64 + 8 pad)
#define STAGE_H (2 * BM * ROWH)       // halves per stage (A + B tiles)
#define GEMM_SMEM (3 * STAGE_H * 2)   // 110592 bytes

// Attention (fp16 mma) smem: Q + 2xK + 2xV tiles (register softmax)
#define AH 72                         // half row stride
#define ATTN_SMEM (5*64*AH*2)         // 46080 bytes

// ---------------- scratch (device globals; no allocation) ----------------
__device__ float  g_X  [NROWS*DD];
__device__ __half g_LN [NROWS*DD];
__device__ __half g_QKV[NROWS*LDA3];     // fused Q|K|V (self and cross), fp16
__device__ __half g_CTX[NROWS*DD];
__device__ __half g_FF [NROWS*FFD];
__device__ __half g_WT [16*1024*1024];   // transposed fp16 weights
__device__ __half g_ENC[BB*SS*DD];       // fp16 encoder activations
__device__ float  g_B3 [3072];           // concat self q|k|v bias
__device__ float  g_B2 [2048];           // concat cross k|v bias

// ---------------- helpers ----------------
__device__ __forceinline__ uint32_t s2u(const void* p) {
    uint32_t a;
    asm("{ .reg .u64 t; cvta.to.shared.u64 t, %1; cvt.u32.u64 %0, t; }" : "=r"(a) : "l"(p));
    return a;
}
__device__ __forceinline__ void cp16(uint32_t dst, const void* src) {
    asm volatile("cp.async.cg.shared.global [%0], [%1], 16;" :: "r"(dst), "l"(src));
}
__device__ __forceinline__ void cp_commit() { asm volatile("cp.async.commit_group;" ::: "memory"); }
template<int N> __device__ __forceinline__ void cp_wait() {
    asm volatile("cp.async.wait_group %0;" :: "n"(N) : "memory");
}
__device__ __forceinline__ void mma16(float* c, const uint32_t* a, const uint32_t* b) {
    asm volatile(
        "mma.sync.aligned.m16n8k16.row.col.f32.f16.f16.f32 "
        "{%0,%1,%2,%3}, {%4,%5,%6,%7}, {%8,%9}, {%0,%1,%2,%3};"
        : "+f"(c[0]), "+f"(c[1]), "+f"(c[2]), "+f"(c[3])
        : "r"(a[0]), "r"(a[1]), "r"(a[2]), "r"(a[3]), "r"(b[0]), "r"(b[1]));
}
#define LDM4(r0, r1, r2, r3, addr) \
    asm volatile("ldmatrix.sync.aligned.m8n8.x4.shared.b16 {%0,%1,%2,%3}, [%4];" \
        : "=r"(r0), "=r"(r1), "=r"(r2), "=r"(r3) : "r"(addr))
#define LDM4T(r0, r1, r2, r3, addr) \
    asm volatile("ldmatrix.sync.aligned.m8n8.x4.trans.shared.b16 {%0,%1,%2,%3}, [%4];" \
        : "=r"(r0), "=r"(r1), "=r"(r2), "=r"(r3) : "r"(addr))

// ---------------- batched transpose + fp16 round + enc copy ----------------
struct TransArgs {
    const float* s[10];
    __half* d[10];
    const float* enc;
    __half* encd;
};
__global__ void transpose_all(TransArgs ta)
{
    __shared__ float tile[32][33];
    int bid = blockIdx.x;
    int tx = threadIdx.x, ty = threadIdx.y;
    if (bid >= 16384) {
        int i = (bid - 16384) * 256 + ty * 32 + tx;
        float4 v = reinterpret_cast<const float4*>(ta.enc)[i];
        reinterpret_cast<__half2*>(ta.encd)[2*i]   = __floats2half2_rn(v.x, v.y);
        reinterpret_cast<__half2*>(ta.encd)[2*i+1] = __floats2half2_rn(v.z, v.w);
        return;
    }
    const float* src; __half* dst; int R, C, bx, by;
    if (bid < 8192) {
        int w = bid >> 10, tt = bid & 1023;
        src = ta.s[w]; dst = ta.d[w]; R = 1024; C = 1024;
        bx = (tt & 31) * 32; by = (tt >> 5) * 32;
    } else if (bid < 12288) {
        int tt = bid - 8192;
        src = ta.s[8]; dst = ta.d[8]; R = 1024; C = 4096;
        bx = (tt & 127) * 32; by = (tt >> 7) * 32;
    } else {
        int tt = bid - 12288;
        src = ta.s[9]; dst = ta.d[9]; R = 4096; C = 1024;
        bx = (tt & 31) * 32; by = (tt >> 5) * 32;
    }
    #pragma unroll
    for (int j = 0; j < 32; j += 8)
        tile[ty + j][tx] = src[(size_t)(by + ty + j) * C + bx + tx];
    __syncthreads();
    #pragma unroll
    for (int j = 0; j < 32; j += 8)
        dst[(size_t)(bx + ty + j) * R + by + tx] = __float2half_rn(tile[tx][ty + j]);
}

// ---------------- LayerNorm (fp32 in, fp16 out; feeds GEMMs only) -------
__global__ void ln_kernel(const float* __restrict__ x,
                          const float* __restrict__ g,
                          const float* __restrict__ b,
                          __half* __restrict__ y)
{
    int row = blockIdx.x;
    int t = threadIdx.x;
    const float4* xr = reinterpret_cast<const float4*>(x + (size_t)row * DD);
    float4 v = xr[t];
    float s  = v.x + v.y + v.z + v.w;
    float ss = v.x*v.x + v.y*v.y + v.z*v.z + v.w*v.w;
    #pragma unroll
    for (int o = 16; o > 0; o >>= 1) {
        s  += __shfl_xor_sync(0xffffffffu, s,  o);
        ss += __shfl_xor_sync(0xffffffffu, ss, o);
    }
    __shared__ float ws[8], wss[8];
    __shared__ float s_mu, s_rstd;
    int lane = t & 31, wid = t >> 5;
    if (lane == 0) { ws[wid] = s; wss[wid] = ss; }
    __syncthreads();
    if (t == 0) {
        float S = 0.f, SS2 = 0.f;
        #pragma unroll
        for (int i = 0; i < 8; i++) { S += ws[i]; SS2 += wss[i]; }
        float mu = S * (1.0f / DD);
        float var = SS2 * (1.0f / DD) - mu * mu;
        s_mu = mu;
        s_rstd = rsqrtf(var + 1e-5f);
    }
    __syncthreads();
    float mu = s_mu, rstd = s_rstd;
    float4 gg = reinterpret_cast<const float4*>(g)[t];
    float4 bb = reinterpret_cast<const float4*>(b)[t];
    __half2* yr = reinterpret_cast<__half2*>(y + (size_t)row * DD);
    yr[2*t]   = __floats2half2_rn((v.x - mu) * rstd * gg.x + bb.x,
                                  (v.y - mu) * rstd * gg.y + bb.y);
    yr[2*t+1] = __floats2half2_rn((v.z - mu) * rstd * gg.z + bb.z,
                                  (v.w - mu) * rstd * gg.w + bb.w);
}

// ---------------- fp16 mma.sync GEMM (ldmatrix + interleaved prefetch) --
// C[Nrows, Mout] = A[Nrows, K] @ WT[Mout, K]^T + bias (+relu / +res)
// EPI: 1 = bias+relu -> half, 2 = bias+residual -> float, 4 = bias -> half
template<int EPI>
__global__ __launch_bounds__(256, 2)
void gemm_h(const __half* __restrict__ A, const __half* __restrict__ WT,
            const float* __restrict__ bias, const float* __restrict__ res,
            void* __restrict__ Cv, int K, int Mout, int ldc)
{
    extern __shared__ __half smh[];
    const int t = threadIdx.x;
    const int wid = t >> 5, lane = t & 31;
    const int g = lane >> 2, tig = lane & 3;
    const int wm = (wid & 1) * 64;
    const int wn = (wid >> 1) * 32;
    const int n0 = blockIdx.y * BM;
    const int m0 = blockIdx.x * BN;

    const __half* Ab = A  + (size_t)n0 * K;
    const __half* Bb = WT + (size_t)m0 * K;

    const int ldrow = t >> 1;
    const int ldseg = (t & 1) * 32;

    const int laneq = lane >> 3;
    const int lrow8 = lane & 7;
    const int aoff0 = (wm + lrow8 + (laneq & 1) * 8) * ROWH + (laneq >> 1) * 8;
    const int boff0 = BM * ROWH + (wn + lrow8 + (laneq >> 1) * 8) * ROWH + (laneq & 1) * 8;

    float c[4][4][4];
    #pragma unroll
    for (int i = 0; i < 4; i++)
        #pragma unroll
        for (int j = 0; j < 4; j++)
            #pragma unroll
            for (int r = 0; r < 4; r++) c[i][j][r] = 0.f;

    const int NIter = K / BKH;
    uint32_t smbase = s2u(smh);

    #pragma unroll
    for (int p = 0; p < 2; p++) {
        uint32_t sA = smbase + p * STAGE_H * 2;
        uint32_t sB = sA + BM * ROWH * 2;
        const __half* Ak = Ab + p * BKH;
        const __half* Bk = Bb + p * BKH;
        #pragma unroll
        for (int q = 0; q < 2; q++) {
            int seg = ldseg + q * 16;
            cp16(sA + (ldrow * ROWH + seg) * 2,      Ak + (size_t)ldrow * K + seg);
            cp16(sA + (ldrow * ROWH + seg + 8) * 2,  Ak + (size_t)ldrow * K + seg + 8);
            cp16(sB + (ldrow * ROWH + seg) * 2,      Bk + (size_t)ldrow * K + seg);
            cp16(sB + (ldrow * ROWH + seg + 8) * 2,  Bk + (size_t)ldrow * K + seg + 8);
        }
        cp_commit();
    }

    for (int i = 0; i < NIter; i++) {
        cp_wait<1>();
        __syncthreads();

        uint32_t stg = smbase + (uint32_t)((i % 3) * STAGE_H * 2);

        // ks = 0 compute
        {
            uint32_t a[4][4], b[4][2];
            uint32_t aaddr = stg + (uint32_t)(aoff0 * 2);
            #pragma unroll
            for (int fi = 0; fi < 4; fi++)
                LDM4(a[fi][0], a[fi][1], a[fi][2], a[fi][3],
                     aaddr + (uint32_t)(fi * 16 * ROWH * 2));
            uint32_t baddr = stg + (uint32_t)(boff0 * 2);
            #pragma unroll
            for (int p = 0; p < 2; p++) {
                uint32_t r0, r1, r2, r3;
                LDM4(r0, r1, r2, r3, baddr + (uint32_t)(p * 16 * ROWH * 2));
                b[2*p][0] = r0;   b[2*p][1] = r1;
                b[2*p+1][0] = r2; b[2*p+1][1] = r3;
            }
            #pragma unroll
            for (int fi = 0; fi < 4; fi++)
                #pragma unroll
                for (int fj = 0; fj < 4; fj++)
                    mma16(c[fi][fj], a[fi], b[fj]);
        }

        // issue prefetch for i+2
        int ip = i + 2;
        if (ip < NIter) {
            int s = ip % 3;
            uint32_t sA = smbase + s * STAGE_H * 2;
            uint32_t sB = sA + BM * ROWH * 2;
            const __half* Ak = Ab + ip * BKH;
            const __half* Bk = Bb + ip * BKH;
            #pragma unroll
            for (int q = 0; q < 2; q++) {
                int seg = ldseg + q * 16;
                cp16(sA + (ldrow * ROWH + seg) * 2,      Ak + (size_t)ldrow * K + seg);
                cp16(sA + (ldrow * ROWH + seg + 8) * 2,  Ak + (size_t)ldrow * K + seg + 8);
                cp16(sB + (ldrow * ROWH + seg) * 2,      Bk + (size_t)ldrow * K + seg);
                cp16(sB + (ldrow * ROWH + seg + 8) * 2,  Bk + (size_t)ldrow * K + seg + 8);
            }
        }
        cp_commit();

        // ks = 1..3 compute
        #pragma unroll
        for (int ks = 1; ks < 4; ks++) {
            uint32_t a[4][4], b[4][2];
            uint32_t aaddr = stg + (uint32_t)((aoff0 + ks * 16) * 2);
            #pragma unroll
            for (int fi = 0; fi < 4; fi++)
                LDM4(a[fi][0], a[fi][1], a[fi][2], a[fi][3],
                     aaddr + (uint32_t)(fi * 16 * ROWH * 2));
            uint32_t baddr = stg + (uint32_t)((boff0 + ks * 16) * 2);
            #pragma unroll
            for (int p = 0; p < 2; p++) {
                uint32_t r0, r1, r2, r3;
                LDM4(r0, r1, r2, r3, baddr + (uint32_t)(p * 16 * ROWH * 2));
                b[2*p][0] = r0;   b[2*p][1] = r1;
                b[2*p+1][0] = r2; b[2*p+1][1] = r3;
            }
            #pragma unroll
            for (int fi = 0; fi < 4; fi++)
                #pragma unroll
                for (int fj = 0; fj < 4; fj++)
                    mma16(c[fi][fj], a[fi], b[fj]);
        }
    }

    #pragma unroll
    for (int fi = 0; fi < 4; fi++) {
        #pragma unroll
        for (int fj = 0; fj < 4; fj++) {
            int row = n0 + wm + 16 * fi + g;
            int col = m0 + wn + 8 * fj + 2 * tig;
            float b0 = __ldg(bias + col), b1 = __ldg(bias + col + 1);
            float v00 = c[fi][fj][0] + b0, v01 = c[fi][fj][1] + b1;
            float v10 = c[fi][fj][2] + b0, v11 = c[fi][fj][3] + b1;
            size_t o0 = (size_t)row * ldc + col;
            size_t o1 = (size_t)(row + 8) * ldc + col;
            if (EPI == 1) {
                __half* Ch = reinterpret_cast<__half*>(Cv);
                *reinterpret_cast<__half2*>(Ch + o0) =
                    __floats2half2_rn(fmaxf(v00, 0.f), fmaxf(v01, 0.f));
                *reinterpret_cast<__half2*>(Ch + o1) =
                    __floats2half2_rn(fmaxf(v10, 0.f), fmaxf(v11, 0.f));
            } else if (EPI == 2) {
                float* Cf = reinterpret_cast<float*>(Cv);
                float2 r0 = *reinterpret_cast<const float2*>(res + o0);
                float2 r1 = *reinterpret_cast<const float2*>(res + o1);
                *reinterpret_cast<float2*>(Cf + o0) = make_float2(v00 + r0.x, v01 + r0.y);
                *reinterpret_cast<float2*>(Cf + o1) = make_float2(v10 + r1.x, v11 + r1.y);
            } else {
                __half* Ch = reinterpret_cast<__half*>(Cv);
                *reinterpret_cast<__half2*>(Ch + o0) = __floats2half2_rn(v00, v01);
                *reinterpret_cast<__half2*>(Ch + o1) = __floats2half2_rn(v10, v11);
            }
        }
    }
}

// ---------------- Flash attention, fp16 mma + reg softmax + 2-stage K/V -
template<bool CAUSAL>
__global__ __launch_bounds__(128, 4)
void attn_h(const __half* __restrict__ Q,
            const __half* __restrict__ K,
            const __half* __restrict__ V,
            __half* __restrict__ O,
            int SKV)
{
    extern __shared__ char smraw[];
    __half* Qs = reinterpret_cast<__half*>(smraw);
    __half* Ks = Qs + 64 * AH;          // 2 stages of 64 rows
    __half* Vs = Ks + 2 * 64 * AH;      // 2 stages of 64 rows

    const int t = threadIdx.x;
    const int wid = t >> 5, lane = t & 31;
    const int g = lane >> 2, tig = lane & 3;
    const int wm = wid * 16;

    const int qt = CAUSAL ? ((int)gridDim.x - 1 - (int)blockIdx.x) : blockIdx.x;
    const int bh = blockIdx.y;
    const int b = bh / HH, h = bh % HH;
    const int q0 = qt * 64;

    size_t qbase  = ((size_t)b * TT + q0) * LDA3 + h * HD;
    size_t kvbase = (size_t)b * SKV * LDA3 + h * HD;
    uint32_t sQs = s2u(Qs), sKs = s2u(Ks), sVs = s2u(Vs);

    const int laneq = lane >> 3;
    const int lrow8 = lane & 7;
    const int aoffA = (wm + lrow8 + (laneq & 1) * 8) * AH + (laneq >> 1) * 8;
    const int boffK = (lrow8 + (laneq >> 1) * 8) * AH + (laneq & 1) * 8;
    const uint32_t vlaneoff = (uint32_t)((lrow8 + 8 * (laneq & 1)) * AH * 2 + (laneq >> 1) * 16);
    const uint32_t STGB = (uint32_t)(64 * AH * 2);   // bytes per K/V stage

    #pragma unroll
    for (int c = 0; c < 4; c++) {
        int idx = c * 128 + t;
        int row = idx >> 3, seg = idx & 7;
        *reinterpret_cast<uint4*>(&Qs[row * AH + seg * 8]) =
            *reinterpret_cast<const uint4*>(Q + qbase + (size_t)row * LDA3 + seg * 8);
    }

    float m0 = -3.0e38f, m1 = -3.0e38f, l0 = 0.f, l1 = 0.f;

    float o[8][4];
    #pragma unroll
    for (int fj = 0; fj < 8; fj++)
        #pragma unroll
        for (int r = 0; r < 4; r++) o[fj][r] = 0.f;

    const int ktEnd = CAUSAL ? qt : (SKV / 64 - 1);
    const float CEXP = 0.180336880111124f;   // 0.125 * log2(e)

    // prologue: load kt=0 into stage 0
    #pragma unroll
    for (int c = 0; c < 4; c++) {
        int idx = c * 128 + t;
        int row = idx >> 3, seg = idx & 7;
        cp16(sKs + (row * AH + seg * 8) * 2, K + kvbase + (size_t)row * LDA3 + seg * 8);
        cp16(sVs + (row * AH + seg * 8) * 2, V + kvbase + (size_t)row * LDA3 + seg * 8);
    }
    cp_commit();

    for (int kt = 0; kt <= ktEnd; kt++) {
        const uint32_t soff = (uint32_t)(kt & 1) * STGB;
        // prefetch kt+1 into other stage, then wait for kt
        if (kt < ktEnd) {
            const int k1g = (kt + 1) * 64;
            const uint32_t soff1 = (uint32_t)((kt + 1) & 1) * STGB;
            #pragma unroll
            for (int c = 0; c < 4; c++) {
                int idx = c * 128 + t;
                int row = idx >> 3, seg = idx & 7;
                cp16(sKs + soff1 + (row * AH + seg * 8) * 2,
                     K + kvbase + (size_t)(k1g + row) * LDA3 + seg * 8);
                cp16(sVs + soff1 + (row * AH + seg * 8) * 2,
                     V + kvbase + (size_t)(k1g + row) * LDA3 + seg * 8);
            }
            cp_commit();
            cp_wait<1>();
        } else {
            cp_wait<0>();
        }
        __syncthreads();

        float cS[8][4];
        #pragma unroll
        for (int fj = 0; fj < 8; fj++)
            #pragma unroll
            for (int r = 0; r < 4; r++) cS[fj][r] = 0.f;

        #pragma unroll
        for (int k0 = 0; k0 < 64; k0 += 16) {
            uint32_t a[4];
            LDM4(a[0], a[1], a[2], a[3], sQs + (uint32_t)((aoffA + k0) * 2));
            #pragma unroll
            for (int p = 0; p < 4; p++) {
                uint32_t r0, r1, r2, r3;
                LDM4(r0, r1, r2, r3,
                     sKs + soff + (uint32_t)((boffK + p * 16 * AH + k0) * 2));
                uint32_t b0[2] = { r0, r1 };
                uint32_t b1[2] = { r2, r3 };
                mma16(cS[2*p],     a, b0);
                mma16(cS[2*p + 1], a, b1);
            }
        }

        if (CAUSAL && kt == qt) {
            #pragma unroll
            for (int fj = 0; fj < 8; fj++) {
                int colL = 8 * fj + 2 * tig;
                int r0 = wm + g, r1 = wm + g + 8;
                if (colL     > r0) cS[fj][0] = -1.0e30f;
                if (colL + 1 > r0) cS[fj][1] = -1.0e30f;
                if (colL     > r1) cS[fj][2] = -1.0e30f;
                if (colL + 1 > r1) cS[fj][3] = -1.0e30f;
            }
        }

        float mx0 = -3.0e38f, mx1 = -3.0e38f;
        #pragma unroll
        for (int fj = 0; fj < 8; fj++) {
            mx0 = fmaxf(mx0, fmaxf(cS[fj][0], cS[fj][1]));
            mx1 = fmaxf(mx1, fmaxf(cS[fj][2], cS[fj][3]));
        }
        mx0 = fmaxf(mx0, __shfl_xor_sync(0xffffffffu, mx0, 1));
        mx0 = fmaxf(mx0, __shfl_xor_sync(0xffffffffu, mx0, 2));
        mx1 = fmaxf(mx1, __shfl_xor_sync(0xffffffffu, mx1, 1));
        mx1 = fmaxf(mx1, __shfl_xor_sync(0xffffffffu, mx1, 2));

        float nm0 = fmaxf(m0, mx0), nm1 = fmaxf(m1, mx1);
        float fac0 = __expf(0.125f * (m0 - nm0));
        float fac1 = __expf(0.125f * (m1 - nm1));
        float nb0 = nm0 * CEXP, nb1 = nm1 * CEXP;

        uint32_t pg[8], pg8[8];
        float s0 = 0.f, s1 = 0.f;
        #pragma unroll
        for (int fj = 0; fj < 8; fj++) {
            __half2 x0 = __floats2half2_rn(fmaf(cS[fj][0], CEXP, -nb0),
                                           fmaf(cS[fj][1], CEXP, -nb0));
            __half2 x1 = __floats2half2_rn(fmaf(cS[fj][2], CEXP, -nb1),
                                           fmaf(cS[fj][3], CEXP, -nb1));
            __half2 p0 = h2exp2(x0);
            __half2 p1 = h2exp2(x1);
            pg[fj]  = *reinterpret_cast<uint32_t*>(&p0);
            pg8[fj] = *reinterpret_cast<uint32_t*>(&p1);
            float2 f0 = __half22float2(p0);
            float2 f1 = __half22float2(p1);
            s0 += f0.x + f0.y;
            s1 += f1.x + f1.y;
        }
        s0 += __shfl_xor_sync(0xffffffffu, s0, 1);
        s0 += __shfl_xor_sync(0xffffffffu, s0, 2);
        s1 += __shfl_xor_sync(0xffffffffu, s1, 1);
        s1 += __shfl_xor_sync(0xffffffffu, s1, 2);

        l0 = l0 * fac0 + s0;
        l1 = l1 * fac1 + s1;
        m0 = nm0; m1 = nm1;

        #pragma unroll
        for (int fj = 0; fj < 8; fj++) {
            o[fj][0] *= fac0; o[fj][1] *= fac0;
            o[fj][2] *= fac1; o[fj][3] *= fac1;
        }
        #pragma unroll
        for (int kb = 0; kb < 4; kb++) {
            uint32_t a[4];
            a[0] = pg [2*kb];
            a[1] = pg8[2*kb];
            a[2] = pg [2*kb + 1];
            a[3] = pg8[2*kb + 1];
            #pragma unroll
            for (int p = 0; p < 4; p++) {
                uint32_t r0, r1, r2, r3;
                LDM4T(r0, r1, r2, r3,
                      sVs + soff + vlaneoff + (uint32_t)(kb * 16 * AH * 2 + p * 32));
                uint32_t b0[2] = { r0, r1 };
                uint32_t b1[2] = { r2, r3 };
                mma16(o[2*p],     a, b0);
                mma16(o[2*p + 1], a, b1);
            }
        }
        __syncthreads();   // all warps done with stage (kt&1) before next prefetch reuses it
    }

    float inv_lo = 1.0f / l0;
    float inv_hi = 1.0f / l1;
    #pragma unroll
    for (int fj = 0; fj < 8; fj++) {
        int colL = 8 * fj + 2 * tig;
        size_t off0 = ((size_t)b * TT + q0 + wm + g) * DD + h * HD + colL;
        size_t off1 = ((size_t)b * TT + q0 + wm + g + 8) * DD + h * HD + colL;
        *reinterpret_cast<__half2*>(O + off0) =
            __floats2half2_rn(o[fj][0] * inv_lo, o[fj][1] * inv_lo);
        *reinterpret_cast<__half2*>(O + off1) =
            __floats2half2_rn(o[fj][2] * inv_hi, o[fj][3] * inv_hi);
    }
}

// ---------------- launch ----------------
extern "C" void kernel_launch(void* const* d_in, const int* in_sizes, int n_in,
                              void* d_out, int out_size)
{
    const float* tgt  = (const float*)d_in[0];
    const float* enc  = (const float*)d_in[1];
    const float* s_wq = (const float*)d_in[4];
    const float* s_wk = (const float*)d_in[5];
    const float* s_wv = (const float*)d_in[6];
    const float* s_wo = (const float*)d_in[7];
    const float* s_bq = (const float*)d_in[8];
    const float* s_bk = (const float*)d_in[9];
    const float* s_bv = (const float*)d_in[10];
    const float* s_bo = (const float*)d_in[11];
    const float* c_wq = (const float*)d_in[12];
    const float* c_wk = (const float*)d_in[13];
    const float* c_wv = (const float*)d_in[14];
    const float* c_wo = (const float*)d_in[15];
    const float* c_bq = (const float*)d_in[16];
    const float* c_bk = (const float*)d_in[17];
    const float* c_bv = (const float*)d_in[18];
    const float* c_bo = (const float*)d_in[19];
    const float* f_w1 = (const float*)d_in[20];
    const float* f_b1 = (const float*)d_in[21];
    const float* f_w2 = (const float*)d_in[22];
    const float* f_b2 = (const float*)d_in[23];
    const float* ln1g = (const float*)d_in[24];
    const float* ln1b = (const float*)d_in[25];
    const float* ln2g = (const float*)d_in[26];
    const float* ln2b = (const float*)d_in[27];
    const float* ln3g = (const float*)d_in[28];
    const float* ln3b = (const float*)d_in[29];
    float* out = (float*)d_out;

    float *X, *B3, *B2;
    __half *LN, *QKV, *CTX, *FFb, *WT, *ENC;
    cudaGetSymbolAddress((void**)&X,   g_X);
    cudaGetSymbolAddress((void**)&LN,  g_LN);
    cudaGetSymbolAddress((void**)&QKV, g_QKV);
    cudaGetSymbolAddress((void**)&CTX, g_CTX);
    cudaGetSymbolAddress((void**)&FFb, g_FF);
    cudaGetSymbolAddress((void**)&WT,  g_WT);
    cudaGetSymbolAddress((void**)&ENC, g_ENC);
    cudaGetSymbolAddress((void**)&B3,  g_B3);
    cudaGetSymbolAddress((void**)&B2,  g_B2);

    const size_t M1 = 1024 * 1024;
    __half* WTs3  = WT + 0*M1;   // s_wq|s_wk|s_wv
    __half* WTswo = WT + 3*M1;
    __half* WTcwq = WT + 4*M1;
    __half* WTc2  = WT + 5*M1;   // c_wk|c_wv
    __half* WTcwo = WT + 7*M1;
    __half* WTf1  = WT + 8*M1;
    __half* WTf2  = WT + 12*M1;

    cudaFuncSetAttribute(attn_h<true>,  cudaFuncAttributeMaxDynamicSharedMemorySize, ATTN_SMEM);
    cudaFuncSetAttribute(attn_h<false>, cudaFuncAttributeMaxDynamicSharedMemorySize, ATTN_SMEM);
    cudaFuncSetAttribute(gemm_h<1>, cudaFuncAttributeMaxDynamicSharedMemorySize, GEMM_SMEM);
    cudaFuncSetAttribute(gemm_h<2>, cudaFuncAttributeMaxDynamicSharedMemorySize, GEMM_SMEM);
    cudaFuncSetAttribute(gemm_h<4>, cudaFuncAttributeMaxDynamicSharedMemorySize, GEMM_SMEM);

    // ---- batched weight transpose + enc copy (one launch), bias concat ----
    TransArgs ta;
    ta.s[0] = s_wq; ta.d[0] = WTs3 + 0*M1;
    ta.s[1] = s_wk; ta.d[1] = WTs3 + 1*M1;
    ta.s[2] = s_wv; ta.d[2] = WTs3 + 2*M1;
    ta.s[3] = s_wo; ta.d[3] = WTswo;
    ta.s[4] = c_wq; ta.d[4] = WTcwq;
    ta.s[5] = c_wk; ta.d[5] = WTc2 + 0*M1;
    ta.s[6] = c_wv; ta.d[6] = WTc2 + 1*M1;
    ta.s[7] = c_wo; ta.d[7] = WTcwo;
    ta.s[8] = f_w1; ta.d[8] = WTf1;
    ta.s[9] = f_w2; ta.d[9] = WTf2;
    ta.enc = enc;  ta.encd = ENC;
    transpose_all<<<20480, dim3(32, 8)>>>(ta);
    cudaMemcpyAsync(B3,        s_bq, DD*4, cudaMemcpyDeviceToDevice, 0);
    cudaMemcpyAsync(B3 + 1024, s_bk, DD*4, cudaMemcpyDeviceToDevice, 0);
    cudaMemcpyAsync(B3 + 2048, s_bv, DD*4, cudaMemcpyDeviceToDevice, 0);
    cudaMemcpyAsync(B2,        c_bk, DD*4, cudaMemcpyDeviceToDevice, 0);
    cudaMemcpyAsync(B2 + 1024, c_bv, DD*4, cudaMemcpyDeviceToDevice, 0);

    dim3 blk(256);
    dim3 ablk(128);
    dim3 gQKV(LDA3 / BN, NROWS / BM);   // (24, 32)
    dim3 gKV (2048 / BN, NROWS / BM);   // (16, 32)
    dim3 gPrj(DD / BN,   NROWS / BM);   // (8, 32)
    dim3 gFF1(FFD / BN,  NROWS / BM);   // (32, 32)
    dim3 gAttn(TT / 64, BB * HH);       // (16, 64)

    // ---- self-attention block ----
    ln_kernel<<<NROWS, 256>>>(tgt, ln1g, ln1b, LN);
    gemm_h<4><<<gQKV, blk, GEMM_SMEM>>>(LN, WTs3, B3, nullptr, QKV, DD, LDA3, LDA3);
    attn_h<true><<<gAttn, ablk, ATTN_SMEM>>>(QKV, QKV + 1024, QKV + 2048, CTX, TT);
    gemm_h<2><<<gPrj, blk, GEMM_SMEM>>>(CTX, WTswo, s_bo, tgt, X, DD, DD, DD);

    // ---- cross-attention block ----
    ln_kernel<<<NROWS, 256>>>(X, ln2g, ln2b, LN);
    gemm_h<4><<<gPrj, blk, GEMM_SMEM>>>(LN,  WTcwq, c_bq, nullptr, QKV, DD, DD, LDA3);
    gemm_h<4><<<gKV,  blk, GEMM_SMEM>>>(ENC, WTc2,  B2,  nullptr, QKV + 1024, DD, 2048, LDA3);
    attn_h<false><<<gAttn, ablk, ATTN_SMEM>>>(QKV, QKV + 1024, QKV + 2048, CTX, SS);
    gemm_h<2><<<gPrj, blk, GEMM_SMEM>>>(CTX, WTcwo, c_bo, X, X, DD, DD, DD);

    // ---- FFN block ----
    ln_kernel<<<NROWS, 256>>>(X, ln3g, ln3b, LN);
    gemm_h<1><<<gFF1, blk, GEMM_SMEM>>>(LN, WTf1, f_b1, nullptr, FFb, DD, FFD, FFD);
    gemm_h<2><<<gPrj, blk, GEMM_SMEM>>>(FFb, WTf2, f_b2, X, out, FFD, DD, DD);
}

// round 15
// speedup vs baseline: 1.0642x; 1.0027x over previous
#include <cuda_runtime.h>
#include <cuda_fp16.h>
#include <cstdint>

// Problem constants (fixed by setup_inputs)
#define BB 4
#define TT 1024
#define SS 1024
#define DD 1024
#define HH 16
#define HD 64
#define FFD 4096
#define NROWS (BB*TT)   // 4096
#define LDA3 3072       // fused QKV row stride (halves)

// GEMM tiling (mma.sync fp16, m16n8k16): 128x128 CTA tile, 64x32 warp tile
#define BM 128
#define BN 128
#define BKH 64                        // K halves per stage chunk
#define ROWH 72                       // smem row stride in halves (64 + 8 pad)
#define STAGE_H (2 * BM * ROWH)       // halves per stage (A + B tiles)
#define GEMM_SMEM (3 * STAGE_H * 2)   // 110592 bytes

// Attention (fp16 mma) smem: Q + 2xK + 2xV tiles (register softmax)
#define AH 72                         // half row stride
#define ATTN_SMEM (5*64*AH*2)         // 46080 bytes

// ---------------- scratch (device globals; no allocation) ----------------
__device__ float  g_X  [NROWS*DD];
__device__ __half g_LN [NROWS*DD];
__device__ __half g_QKV[NROWS*LDA3];     // fused Q|K|V (self and cross), fp16
__device__ __half g_CTX[NROWS*DD];
__device__ __half g_FF [NROWS*FFD];
__device__ __half g_WT [16*1024*1024];   // transposed fp16 weights
__device__ __half g_ENC[BB*SS*DD];       // fp16 encoder activations
__device__ float  g_B3 [3072];           // concat self q|k|v bias
__device__ float  g_B2 [3072];           // concat cross q|k|v bias

// ---------------- helpers ----------------
__device__ __forceinline__ uint32_t s2u(const void* p) {
    uint32_t a;
    asm("{ .reg .u64 t; cvta.to.shared.u64 t, %1; cvt.u32.u64 %0, t; }" : "=r"(a) : "l"(p));
    return a;
}
__device__ __forceinline__ void cp16(uint32_t dst, const void* src) {
    asm volatile("cp.async.cg.shared.global [%0], [%1], 16;" :: "r"(dst), "l"(src));
}
__device__ __forceinline__ void cp_commit() { asm volatile("cp.async.commit_group;" ::: "memory"); }
template<int N> __device__ __forceinline__ void cp_wait() {
    asm volatile("cp.async.wait_group %0;" :: "n"(N) : "memory");
}
__device__ __forceinline__ void mma16(float* c, const uint32_t* a, const uint32_t* b) {
    asm volatile(
        "mma.sync.aligned.m16n8k16.row.col.f32.f16.f16.f32 "
        "{%0,%1,%2,%3}, {%4,%5,%6,%7}, {%8,%9}, {%0,%1,%2,%3};"
        : "+f"(c[0]), "+f"(c[1]), "+f"(c[2]), "+f"(c[3])
        : "r"(a[0]), "r"(a[1]), "r"(a[2]), "r"(a[3]), "r"(b[0]), "r"(b[1]));
}
#define LDM4(r0, r1, r2, r3, addr) \
    asm volatile("ldmatrix.sync.aligned.m8n8.x4.shared.b16 {%0,%1,%2,%3}, [%4];" \
        : "=r"(r0), "=r"(r1), "=r"(r2), "=r"(r3) : "r"(addr))
#define LDM4T(r0, r1, r2, r3, addr) \
    asm volatile("ldmatrix.sync.aligned.m8n8.x4.trans.shared.b16 {%0,%1,%2,%3}, [%4];" \
        : "=r"(r0), "=r"(r1), "=r"(r2), "=r"(r3) : "r"(addr))

// ---------------- batched transpose + fp16 round + enc copy ----------------
struct TransArgs {
    const float* s[10];
    __half* d[10];
    const float* enc;
    __half* encd;
};
__global__ void transpose_all(TransArgs ta)
{
    __shared__ float tile[32][33];
    int bid = blockIdx.x;
    int tx = threadIdx.x, ty = threadIdx.y;
    if (bid >= 16384) {
        int i = (bid - 16384) * 256 + ty * 32 + tx;
        float4 v = reinterpret_cast<const float4*>(ta.enc)[i];
        reinterpret_cast<__half2*>(ta.encd)[2*i]   = __floats2half2_rn(v.x, v.y);
        reinterpret_cast<__half2*>(ta.encd)[2*i+1] = __floats2half2_rn(v.z, v.w);
        return;
    }
    const float* src; __half* dst; int R, C, bx, by;
    if (bid < 8192) {
        int w = bid >> 10, tt = bid & 1023;
        src = ta.s[w]; dst = ta.d[w]; R = 1024; C = 1024;
        bx = (tt & 31) * 32; by = (tt >> 5) * 32;
    } else if (bid < 12288) {
        int tt = bid - 8192;
        src = ta.s[8]; dst = ta.d[8]; R = 1024; C = 4096;
        bx = (tt & 127) * 32; by = (tt >> 7) * 32;
    } else {
        int tt = bid - 12288;
        src = ta.s[9]; dst = ta.d[9]; R = 4096; C = 1024;
        bx = (tt & 31) * 32; by = (tt >> 5) * 32;
    }
    #pragma unroll
    for (int j = 0; j < 32; j += 8)
        tile[ty + j][tx] = src[(size_t)(by + ty + j) * C + bx + tx];
    __syncthreads();
    #pragma unroll
    for (int j = 0; j < 32; j += 8)
        dst[(size_t)(bx + ty + j) * R + by + tx] = __float2half_rn(tile[tx][ty + j]);
}

// ---------------- LayerNorm (fp32 in, fp16 out; feeds GEMMs only) -------
__global__ void ln_kernel(const float* __restrict__ x,
                          const float* __restrict__ g,
                          const float* __restrict__ b,
                          __half* __restrict__ y)
{
    int row = blockIdx.x;
    int t = threadIdx.x;
    const float4* xr = reinterpret_cast<const float4*>(x + (size_t)row * DD);
    float4 v = xr[t];
    float s  = v.x + v.y + v.z + v.w;
    float ss = v.x*v.x + v.y*v.y + v.z*v.z + v.w*v.w;
    #pragma unroll
    for (int o = 16; o > 0; o >>= 1) {
        s  += __shfl_xor_sync(0xffffffffu, s,  o);
        ss += __shfl_xor_sync(0xffffffffu, ss, o);
    }
    __shared__ float ws[8], wss[8];
    __shared__ float s_mu, s_rstd;
    int lane = t & 31, wid = t >> 5;
    if (lane == 0) { ws[wid] = s; wss[wid] = ss; }
    __syncthreads();
    if (t == 0) {
        float S = 0.f, SS2 = 0.f;
        #pragma unroll
        for (int i = 0; i < 8; i++) { S += ws[i]; SS2 += wss[i]; }
        float mu = S * (1.0f / DD);
        float var = SS2 * (1.0f / DD) - mu * mu;
        s_mu = mu;
        s_rstd = rsqrtf(var + 1e-5f);
    }
    __syncthreads();
    float mu = s_mu, rstd = s_rstd;
    float4 gg = reinterpret_cast<const float4*>(g)[t];
    float4 bb = reinterpret_cast<const float4*>(b)[t];
    __half2* yr = reinterpret_cast<__half2*>(y + (size_t)row * DD);
    yr[2*t]   = __floats2half2_rn((v.x - mu) * rstd * gg.x + bb.x,
                                  (v.y - mu) * rstd * gg.y + bb.y);
    yr[2*t+1] = __floats2half2_rn((v.z - mu) * rstd * gg.z + bb.z,
                                  (v.w - mu) * rstd * gg.w + bb.w);
}

// ---------------- fp16 mma.sync GEMM (ldmatrix + interleaved prefetch) --
// C[Nrows, Mout] = A[Nrows, K] @ WT[Mout, K]^T + bias (+relu / +res)
// EPI: 1 = bias+relu -> half, 2 = bias+residual -> float, 4 = bias -> half,
//      5 = dual-A (A if m0<1024 else res-as-A1) + bias -> half
template<int EPI>
__global__ __launch_bounds__(256, 2)
void gemm_h(const __half* __restrict__ A, const __half* __restrict__ WT,
            const float* __restrict__ bias, const float* __restrict__ res,
            void* __restrict__ Cv, int K, int Mout, int ldc)
{
    extern __shared__ __half smh[];
    const int t = threadIdx.x;
    const int wid = t >> 5, lane = t & 31;
    const int g = lane >> 2, tig = lane & 3;
    const int wm = (wid & 1) * 64;
    const int wn = (wid >> 1) * 32;
    const int n0 = blockIdx.y * BM;
    const int m0 = blockIdx.x * BN;

    const __half* Asel = (EPI == 5 && m0 >= 1024)
                       ? reinterpret_cast<const __half*>(res) : A;
    const __half* Ab = Asel + (size_t)n0 * K;
    const __half* Bb = WT + (size_t)m0 * K;

    const int ldrow = t >> 1;
    const int ldseg = (t & 1) * 32;

    const int laneq = lane >> 3;
    const int lrow8 = lane & 7;
    const int aoff0 = (wm + lrow8 + (laneq & 1) * 8) * ROWH + (laneq >> 1) * 8;
    const int boff0 = BM * ROWH + (wn + lrow8 + (laneq >> 1) * 8) * ROWH + (laneq & 1) * 8;

    float c[4][4][4];
    #pragma unroll
    for (int i = 0; i < 4; i++)
        #pragma unroll
        for (int j = 0; j < 4; j++)
            #pragma unroll
            for (int r = 0; r < 4; r++) c[i][j][r] = 0.f;

    const int NIter = K / BKH;
    uint32_t smbase = s2u(smh);

    #pragma unroll
    for (int p = 0; p < 2; p++) {
        uint32_t sA = smbase + p * STAGE_H * 2;
        uint32_t sB = sA + BM * ROWH * 2;
        const __half* Ak = Ab + p * BKH;
        const __half* Bk = Bb + p * BKH;
        #pragma unroll
        for (int q = 0; q < 2; q++) {
            int seg = ldseg + q * 16;
            cp16(sA + (ldrow * ROWH + seg) * 2,      Ak + (size_t)ldrow * K + seg);
            cp16(sA + (ldrow * ROWH + seg + 8) * 2,  Ak + (size_t)ldrow * K + seg + 8);
            cp16(sB + (ldrow * ROWH + seg) * 2,      Bk + (size_t)ldrow * K + seg);
            cp16(sB + (ldrow * ROWH + seg + 8) * 2,  Bk + (size_t)ldrow * K + seg + 8);
        }
        cp_commit();
    }

    for (int i = 0; i < NIter; i++) {
        cp_wait<1>();
        __syncthreads();

        uint32_t stg = smbase + (uint32_t)((i % 3) * STAGE_H * 2);

        // ks = 0 compute
        {
            uint32_t a[4][4], b[4][2];
            uint32_t aaddr = stg + (uint32_t)(aoff0 * 2);
            #pragma unroll
            for (int fi = 0; fi < 4; fi++)
                LDM4(a[fi][0], a[fi][1], a[fi][2], a[fi][3],
                     aaddr + (uint32_t)(fi * 16 * ROWH * 2));
            uint32_t baddr = stg + (uint32_t)(boff0 * 2);
            #pragma unroll
            for (int p = 0; p < 2; p++) {
                uint32_t r0, r1, r2, r3;
                LDM4(r0, r1, r2, r3, baddr + (uint32_t)(p * 16 * ROWH * 2));
                b[2*p][0] = r0;   b[2*p][1] = r1;
                b[2*p+1][0] = r2; b[2*p+1][1] = r3;
            }
            #pragma unroll
            for (int fi = 0; fi < 4; fi++)
                #pragma unroll
                for (int fj = 0; fj < 4; fj++)
                    mma16(c[fi][fj], a[fi], b[fj]);
        }

        // issue prefetch for i+2
        int ip = i + 2;
        if (ip < NIter) {
            int s = ip % 3;
            uint32_t sA = smbase + s * STAGE_H * 2;
            uint32_t sB = sA + BM * ROWH * 2;
            const __half* Ak = Ab + ip * BKH;
            const __half* Bk = Bb + ip * BKH;
            #pragma unroll
            for (int q = 0; q < 2; q++) {
                int seg = ldseg + q * 16;
                cp16(sA + (ldrow * ROWH + seg) * 2,      Ak + (size_t)ldrow * K + seg);
                cp16(sA + (ldrow * ROWH + seg + 8) * 2,  Ak + (size_t)ldrow * K + seg + 8);
                cp16(sB + (ldrow * ROWH + seg) * 2,      Bk + (size_t)ldrow * K + seg);
                cp16(sB + (ldrow * ROWH + seg + 8) * 2,  Bk + (size_t)ldrow * K + seg + 8);
            }
        }
        cp_commit();

        // ks = 1..3 compute
        #pragma unroll
        for (int ks = 1; ks < 4; ks++) {
            uint32_t a[4][4], b[4][2];
            uint32_t aaddr = stg + (uint32_t)((aoff0 + ks * 16) * 2);
            #pragma unroll
            for (int fi = 0; fi < 4; fi++)
                LDM4(a[fi][0], a[fi][1], a[fi][2], a[fi][3],
                     aaddr + (uint32_t)(fi * 16 * ROWH * 2));
            uint32_t baddr = stg + (uint32_t)((boff0 + ks * 16) * 2);
            #pragma unroll
            for (int p = 0; p < 2; p++) {
                uint32_t r0, r1, r2, r3;
                LDM4(r0, r1, r2, r3, baddr + (uint32_t)(p * 16 * ROWH * 2));
                b[2*p][0] = r0;   b[2*p][1] = r1;
                b[2*p+1][0] = r2; b[2*p+1][1] = r3;
            }
            #pragma unroll
            for (int fi = 0; fi < 4; fi++)
                #pragma unroll
                for (int fj = 0; fj < 4; fj++)
                    mma16(c[fi][fj], a[fi], b[fj]);
        }
    }

    #pragma unroll
    for (int fi = 0; fi < 4; fi++) {
        #pragma unroll
        for (int fj = 0; fj < 4; fj++) {
            int row = n0 + wm + 16 * fi + g;
            int col = m0 + wn + 8 * fj + 2 * tig;
            float b0 = __ldg(bias + col), b1 = __ldg(bias + col + 1);
            float v00 = c[fi][fj][0] + b0, v01 = c[fi][fj][1] + b1;
            float v10 = c[fi][fj][2] + b0, v11 = c[fi][fj][3] + b1;
            size_t o0 = (size_t)row * ldc + col;
            size_t o1 = (size_t)(row + 8) * ldc + col;
            if (EPI == 1) {
                __half* Ch = reinterpret_cast<__half*>(Cv);
                *reinterpret_cast<__half2*>(Ch + o0) =
                    __floats2half2_rn(fmaxf(v00, 0.f), fmaxf(v01, 0.f));
                *reinterpret_cast<__half2*>(Ch + o1) =
                    __floats2half2_rn(fmaxf(v10, 0.f), fmaxf(v11, 0.f));
            } else if (EPI == 2) {
                float* Cf = reinterpret_cast<float*>(Cv);
                float2 r0 = *reinterpret_cast<const float2*>(res + o0);
                float2 r1 = *reinterpret_cast<const float2*>(res + o1);
                *reinterpret_cast<float2*>(Cf + o0) = make_float2(v00 + r0.x, v01 + r0.y);
                *reinterpret_cast<float2*>(Cf + o1) = make_float2(v10 + r1.x, v11 + r1.y);
            } else {
                __half* Ch = reinterpret_cast<__half*>(Cv);
                *reinterpret_cast<__half2*>(Ch + o0) = __floats2half2_rn(v00, v01);
                *reinterpret_cast<__half2*>(Ch + o1) = __floats2half2_rn(v10, v11);
            }
        }
    }
}

// ---------------- Flash attention, fp16 mma + reg softmax + 2-stage K/V -
template<bool CAUSAL>
__global__ __launch_bounds__(128, 4)
void attn_h(const __half* __restrict__ Q,
            const __half* __restrict__ K,
            const __half* __restrict__ V,
            __half* __restrict__ O,
            int SKV)
{
    extern __shared__ char smraw[];
    __half* Qs = reinterpret_cast<__half*>(smraw);
    __half* Ks = Qs + 64 * AH;          // 2 stages of 64 rows
    __half* Vs = Ks + 2 * 64 * AH;      // 2 stages of 64 rows

    const int t = threadIdx.x;
    const int wid = t >> 5, lane = t & 31;
    const int g = lane >> 2, tig = lane & 3;
    const int wm = wid * 16;

    const int qt = CAUSAL ? ((int)gridDim.x - 1 - (int)blockIdx.x) : blockIdx.x;
    const int bh = blockIdx.y;
    const int b = bh / HH, h = bh % HH;
    const int q0 = qt * 64;

    size_t qbase  = ((size_t)b * TT + q0) * LDA3 + h * HD;
    size_t kvbase = (size_t)b * SKV * LDA3 + h * HD;
    uint32_t sQs = s2u(Qs), sKs = s2u(Ks), sVs = s2u(Vs);

    const int laneq = lane >> 3;
    const int lrow8 = lane & 7;
    const int aoffA = (wm + lrow8 + (laneq & 1) * 8) * AH + (laneq >> 1) * 8;
    const int boffK = (lrow8 + (laneq >> 1) * 8) * AH + (laneq & 1) * 8;
    const uint32_t vlaneoff = (uint32_t)((lrow8 + 8 * (laneq & 1)) * AH * 2 + (laneq >> 1) * 16);
    const uint32_t STGB = (uint32_t)(64 * AH * 2);   // bytes per K/V stage

    #pragma unroll
    for (int c = 0; c < 4; c++) {
        int idx = c * 128 + t;
        int row = idx >> 3, seg = idx & 7;
        *reinterpret_cast<uint4*>(&Qs[row * AH + seg * 8]) =
            *reinterpret_cast<const uint4*>(Q + qbase + (size_t)row * LDA3 + seg * 8);
    }

    float m0 = -3.0e38f, m1 = -3.0e38f, l0 = 0.f, l1 = 0.f;

    float o[8][4];
    #pragma unroll
    for (int fj = 0; fj < 8; fj++)
        #pragma unroll
        for (int r = 0; r < 4; r++) o[fj][r] = 0.f;

    const int ktEnd = CAUSAL ? qt : (SKV / 64 - 1);
    const float CEXP = 0.180336880111124f;   // 0.125 * log2(e)

    // prologue: load kt=0 into stage 0
    #pragma unroll
    for (int c = 0; c < 4; c++) {
        int idx = c * 128 + t;
        int row = idx >> 3, seg = idx & 7;
        cp16(sKs + (row * AH + seg * 8) * 2, K + kvbase + (size_t)row * LDA3 + seg * 8);
        cp16(sVs + (row * AH + seg * 8) * 2, V + kvbase + (size_t)row * LDA3 + seg * 8);
    }
    cp_commit();

    for (int kt = 0; kt <= ktEnd; kt++) {
        const uint32_t soff = (uint32_t)(kt & 1) * STGB;
        if (kt < ktEnd) {
            const int k1g = (kt + 1) * 64;
            const uint32_t soff1 = (uint32_t)((kt + 1) & 1) * STGB;
            #pragma unroll
            for (int c = 0; c < 4; c++) {
                int idx = c * 128 + t;
                int row = idx >> 3, seg = idx & 7;
                cp16(sKs + soff1 + (row * AH + seg * 8) * 2,
                     K + kvbase + (size_t)(k1g + row) * LDA3 + seg * 8);
                cp16(sVs + soff1 + (row * AH + seg * 8) * 2,
                     V + kvbase + (size_t)(k1g + row) * LDA3 + seg * 8);
            }
            cp_commit();
            cp_wait<1>();
        } else {
            cp_wait<0>();
        }
        __syncthreads();

        float cS[8][4];
        #pragma unroll
        for (int fj = 0; fj < 8; fj++)
            #pragma unroll
            for (int r = 0; r < 4; r++) cS[fj][r] = 0.f;

        #pragma unroll
        for (int k0 = 0; k0 < 64; k0 += 16) {
            uint32_t a[4];
            LDM4(a[0], a[1], a[2], a[3], sQs + (uint32_t)((aoffA + k0) * 2));
            #pragma unroll
            for (int p = 0; p < 4; p++) {
                uint32_t r0, r1, r2, r3;
                LDM4(r0, r1, r2, r3,
                     sKs + soff + (uint32_t)((boffK + p * 16 * AH + k0) * 2));
                uint32_t b0[2] = { r0, r1 };
                uint32_t b1[2] = { r2, r3 };
                mma16(cS[2*p],     a, b0);
                mma16(cS[2*p + 1], a, b1);
            }
        }

        if (CAUSAL && kt == qt) {
            #pragma unroll
            for (int fj = 0; fj < 8; fj++) {
                int colL = 8 * fj + 2 * tig;
                int r0 = wm + g, r1 = wm + g + 8;
                if (colL     > r0) cS[fj][0] = -1.0e30f;
                if (colL + 1 > r0) cS[fj][1] = -1.0e30f;
                if (colL     > r1) cS[fj][2] = -1.0e30f;
                if (colL + 1 > r1) cS[fj][3] = -1.0e30f;
            }
        }

        float mx0 = -3.0e38f, mx1 = -3.0e38f;
        #pragma unroll
        for (int fj = 0; fj < 8; fj++) {
            mx0 = fmaxf(mx0, fmaxf(cS[fj][0], cS[fj][1]));
            mx1 = fmaxf(mx1, fmaxf(cS[fj][2], cS[fj][3]));
        }
        mx0 = fmaxf(mx0, __shfl_xor_sync(0xffffffffu, mx0, 1));
        mx0 = fmaxf(mx0, __shfl_xor_sync(0xffffffffu, mx0, 2));
        mx1 = fmaxf(mx1, __shfl_xor_sync(0xffffffffu, mx1, 1));
        mx1 = fmaxf(mx1, __shfl_xor_sync(0xffffffffu, mx1, 2));

        float nm0 = fmaxf(m0, mx0), nm1 = fmaxf(m1, mx1);
        float fac0 = __expf(0.125f * (m0 - nm0));
        float fac1 = __expf(0.125f * (m1 - nm1));
        float nb0 = nm0 * CEXP, nb1 = nm1 * CEXP;

        uint32_t pg[8], pg8[8];
        float s0 = 0.f, s1 = 0.f;
        #pragma unroll
        for (int fj = 0; fj < 8; fj++) {
            __half2 x0 = __floats2half2_rn(fmaf(cS[fj][0], CEXP, -nb0),
                                           fmaf(cS[fj][1], CEXP, -nb0));
            __half2 x1 = __floats2half2_rn(fmaf(cS[fj][2], CEXP, -nb1),
                                           fmaf(cS[fj][3], CEXP, -nb1));
            __half2 p0 = h2exp2(x0);
            __half2 p1 = h2exp2(x1);
            pg[fj]  = *reinterpret_cast<uint32_t*>(&p0);
            pg8[fj] = *reinterpret_cast<uint32_t*>(&p1);
            float2 f0 = __half22float2(p0);
            float2 f1 = __half22float2(p1);
            s0 += f0.x + f0.y;
            s1 += f1.x + f1.y;
        }
        s0 += __shfl_xor_sync(0xffffffffu, s0, 1);
        s0 += __shfl_xor_sync(0xffffffffu, s0, 2);
        s1 += __shfl_xor_sync(0xffffffffu, s1, 1);
        s1 += __shfl_xor_sync(0xffffffffu, s1, 2);

        l0 = l0 * fac0 + s0;
        l1 = l1 * fac1 + s1;
        m0 = nm0; m1 = nm1;

        #pragma unroll
        for (int fj = 0; fj < 8; fj++) {
            o[fj][0] *= fac0; o[fj][1] *= fac0;
            o[fj][2] *= fac1; o[fj][3] *= fac1;
        }
        #pragma unroll
        for (int kb = 0; kb < 4; kb++) {
            uint32_t a[4];
            a[0] = pg [2*kb];
            a[1] = pg8[2*kb];
            a[2] = pg [2*kb + 1];
            a[3] = pg8[2*kb + 1];
            #pragma unroll
            for (int p = 0; p < 4; p++) {
                uint32_t r0, r1, r2, r3;
                LDM4T(r0, r1, r2, r3,
                      sVs + soff + vlaneoff + (uint32_t)(kb * 16 * AH * 2 + p * 32));
                uint32_t b0[2] = { r0, r1 };
                uint32_t b1[2] = { r2, r3 };
                mma16(o[2*p],     a, b0);
                mma16(o[2*p + 1], a, b1);
            }
        }
        __syncthreads();
    }

    float inv_lo = 1.0f / l0;
    float inv_hi = 1.0f / l1;
    #pragma unroll
    for (int fj = 0; fj < 8; fj++) {
        int colL = 8 * fj + 2 * tig;
        size_t off0 = ((size_t)b * TT + q0 + wm + g) * DD + h * HD + colL;
        size_t off1 = ((size_t)b * TT + q0 + wm + g + 8) * DD + h * HD + colL;
        *reinterpret_cast<__half2*>(O + off0) =
            __floats2half2_rn(o[fj][0] * inv_lo, o[fj][1] * inv_lo);
        *reinterpret_cast<__half2*>(O + off1) =
            __floats2half2_rn(o[fj][2] * inv_hi, o[fj][3] * inv_hi);
    }
}

// ---------------- launch ----------------
extern "C" void kernel_launch(void* const* d_in, const int* in_sizes, int n_in,
                              void* d_out, int out_size)
{
    const float* tgt  = (const float*)d_in[0];
    const float* enc  = (const float*)d_in[1];
    const float* s_wq = (const float*)d_in[4];
    const float* s_wk = (const float*)d_in[5];
    const float* s_wv = (const float*)d_in[6];
    const float* s_wo = (const float*)d_in[7];
    const float* s_bq = (const float*)d_in[8];
    const float* s_bk = (const float*)d_in[9];
    const float* s_bv = (const float*)d_in[10];
    const float* s_bo = (const float*)d_in[11];
    const float* c_wq = (const float*)d_in[12];
    const float* c_wk = (const float*)d_in[13];
    const float* c_wv = (const float*)d_in[14];
    const float* c_wo = (const float*)d_in[15];
    const float* c_bq = (const float*)d_in[16];
    const float* c_bk = (const float*)d_in[17];
    const float* c_bv = (const float*)d_in[18];
    const float* c_bo = (const float*)d_in[19];
    const float* f_w1 = (const float*)d_in[20];
    const float* f_b1 = (const float*)d_in[21];
    const float* f_w2 = (const float*)d_in[22];
    const float* f_b2 = (const float*)d_in[23];
    const float* ln1g = (const float*)d_in[24];
    const float* ln1b = (const float*)d_in[25];
    const float* ln2g = (const float*)d_in[26];
    const float* ln2b = (const float*)d_in[27];
    const float* ln3g = (const float*)d_in[28];
    const float* ln3b = (const float*)d_in[29];
    float* out = (float*)d_out;

    float *X, *B3, *B2;
    __half *LN, *QKV, *CTX, *FFb, *WT, *ENC;
    cudaGetSymbolAddress((void**)&X,   g_X);
    cudaGetSymbolAddress((void**)&LN,  g_LN);
    cudaGetSymbolAddress((void**)&QKV, g_QKV);
    cudaGetSymbolAddress((void**)&CTX, g_CTX);
    cudaGetSymbolAddress((void**)&FFb, g_FF);
    cudaGetSymbolAddress((void**)&WT,  g_WT);
    cudaGetSymbolAddress((void**)&ENC, g_ENC);
    cudaGetSymbolAddress((void**)&B3,  g_B3);
    cudaGetSymbolAddress((void**)&B2,  g_B2);

    const size_t M1 = 1024 * 1024;
    __half* WTs3  = WT + 0*M1;   // s_wq|s_wk|s_wv
    __half* WTswo = WT + 3*M1;
    __half* WTc3  = WT + 4*M1;   // c_wq|c_wk|c_wv (contiguous, 3M)
    __half* WTcwo = WT + 7*M1;
    __half* WTf1  = WT + 8*M1;
    __half* WTf2  = WT + 12*M1;

    cudaFuncSetAttribute(attn_h<true>,  cudaFuncAttributeMaxDynamicSharedMemorySize, ATTN_SMEM);
    cudaFuncSetAttribute(attn_h<false>, cudaFuncAttributeMaxDynamicSharedMemorySize, ATTN_SMEM);
    cudaFuncSetAttribute(gemm_h<1>, cudaFuncAttributeMaxDynamicSharedMemorySize, GEMM_SMEM);
    cudaFuncSetAttribute(gemm_h<2>, cudaFuncAttributeMaxDynamicSharedMemorySize, GEMM_SMEM);
    cudaFuncSetAttribute(gemm_h<4>, cudaFuncAttributeMaxDynamicSharedMemorySize, GEMM_SMEM);
    cudaFuncSetAttribute(gemm_h<5>, cudaFuncAttributeMaxDynamicSharedMemorySize, GEMM_SMEM);

    // ---- batched weight transpose + enc copy (one launch), bias concat ----
    TransArgs ta;
    ta.s[0] = s_wq; ta.d[0] = WTs3 + 0*M1;
    ta.s[1] = s_wk; ta.d[1] = WTs3 + 1*M1;
    ta.s[2] = s_wv; ta.d[2] = WTs3 + 2*M1;
    ta.s[3] = s_wo; ta.d[3] = WTswo;
    ta.s[4] = c_wq; ta.d[4] = WTc3 + 0*M1;
    ta.s[5] = c_wk; ta.d[5] = WTc3 + 1*M1;
    ta.s[6] = c_wv; ta.d[6] = WTc3 + 2*M1;
    ta.s[7] = c_wo; ta.d[7] = WTcwo;
    ta.s[8] = f_w1; ta.d[8] = WTf1;
    ta.s[9] = f_w2; ta.d[9] = WTf2;
    ta.enc = enc;  ta.encd = ENC;
    transpose_all<<<20480, dim3(32, 8)>>>(ta);
    cudaMemcpyAsync(B3,        s_bq, DD*4, cudaMemcpyDeviceToDevice, 0);
    cudaMemcpyAsync(B3 + 1024, s_bk, DD*4, cudaMemcpyDeviceToDevice, 0);
    cudaMemcpyAsync(B3 + 2048, s_bv, DD*4, cudaMemcpyDeviceToDevice, 0);
    cudaMemcpyAsync(B2,        c_bq, DD*4, cudaMemcpyDeviceToDevice, 0);
    cudaMemcpyAsync(B2 + 1024, c_bk, DD*4, cudaMemcpyDeviceToDevice, 0);
    cudaMemcpyAsync(B2 + 2048, c_bv, DD*4, cudaMemcpyDeviceToDevice, 0);

    dim3 blk(256);
    dim3 ablk(128);
    dim3 gQKV(LDA3 / BN, NROWS / BM);   // (24, 32)
    dim3 gPrj(DD / BN,   NROWS / BM);   // (8, 32)
    dim3 gFF1(FFD / BN,  NROWS / BM);   // (32, 32)
    dim3 gAttn(TT / 64, BB * HH);       // (16, 64)

    // ---- self-attention block ----
    ln_kernel<<<NROWS, 256>>>(tgt, ln1g, ln1b, LN);
    gemm_h<4><<<gQKV, blk, GEMM_SMEM>>>(LN, WTs3, B3, nullptr, QKV, DD, LDA3, LDA3);
    attn_h<true><<<gAttn, ablk, ATTN_SMEM>>>(QKV, QKV + 1024, QKV + 2048, CTX, TT);
    gemm_h<2><<<gPrj, blk, GEMM_SMEM>>>(CTX, WTswo, s_bo, tgt, X, DD, DD, DD);

    // ---- cross-attention block (Q + K|V projections fused: dual-A) ----
    ln_kernel<<<NROWS, 256>>>(X, ln2g, ln2b, LN);
    gemm_h<5><<<gQKV, blk, GEMM_SMEM>>>(LN, WTc3, B2, (const float*)ENC, QKV, DD, LDA3, LDA3);
    attn_h<false><<<gAttn, ablk, ATTN_SMEM>>>(QKV, QKV + 1024, QKV + 2048, CTX, SS);
    gemm_h<2><<<gPrj, blk, GEMM_SMEM>>>(CTX, WTcwo, c_bo, X, X, DD, DD, DD);

    // ---- FFN block ----
    ln_kernel<<<NROWS, 256>>>(X, ln3g, ln3b, LN);
    gemm_h<1><<<gFF1, blk, GEMM_SMEM>>>(LN, WTf1, f_b1, nullptr, FFb, DD, FFD, FFD);
    gemm_h<2><<<gPrj, blk, GEMM_SMEM>>>(FFb, WTf2, f_b2, X, out, FFD, DD, DD);
}